// round 1
// baseline (speedup 1.0000x reference)
#include <cuda_runtime.h>
#include <math.h>

#define EPS 1e-5f

// Problem constants
#define BATCH 4
#define HH 64
#define WW 64
#define HW 4096          // 64*64
#define CC 512
#define KK 19
#define PP 64            // patches
#define NN 64            // pixels per patch
#define DD 256           // qkv dim
#define CIN3 2560        // 512 + 2048

// ---------------- scratch (static device memory; no allocations) ----------------
__device__ float g_Fnhwc[BATCH * HW * CC];           // F transposed to NHWC
__device__ float g_cat[(size_t)BATCH * HW * CIN3];   // cols [0,512): x2, [512,2560): M1
__device__ float g_Fl[BATCH * PP * KK * CC];         // F_l
__device__ float g_h[BATCH * PP * KK * CC];          // relu(lg_w1@F_l + F_l)
__device__ float g_Fl2[BATCH * PP * KK * CC];        // h @ lg_w2^T
__device__ float g_Fg[BATCH * KK * CC];              // fused
__device__ float g_query[BATCH * HW * DD];
__device__ float g_key[BATCH * PP * KK * DD];
__device__ float g_value[BATCH * KK * DD];
__device__ float g_Fs[BATCH * HW * DD];              // attention out, NHWC
__device__ float g_Fo1[BATCH * HW * CC];             // after c1 + residual
__device__ float g_x3[BATCH * HW * CC];              // after c3

// ---------------- transpose NCHW -> NHWC (with column offset / stride) ----------------
__global__ void k_transpose(const float* __restrict__ in, float* __restrict__ out,
                            int C, int out_stride, int col_off) {
    __shared__ float tile[32][33];
    int b = blockIdx.z;
    int hw0 = blockIdx.x * 32, c0 = blockIdx.y * 32;
    int tx = threadIdx.x, ty = threadIdx.y; // 32 x 8
    for (int i = ty; i < 32; i += 8)
        tile[i][tx] = in[((size_t)b * C + c0 + i) * HW + hw0 + tx];
    __syncthreads();
    for (int i = ty; i < 32; i += 8)
        out[((size_t)b * HW + hw0 + i) * out_stride + col_off + c0 + tx] = tile[tx][i];
}

// ---------------- kernel A: patch softmax + F_l = (pix^T F_p) * bin_conf ----------------
__global__ void k_patch_fl(const float* __restrict__ I, const float* __restrict__ R) {
    int bp = blockIdx.x;
    int b = bp >> 6, p = bp & 63;
    int ph = p >> 3, pw = p & 7;
    int tid = threadIdx.x;

    __shared__ float lg[KK][NN];
    __shared__ float pix[NN][20];
    __shared__ float bc[KK];
    __shared__ float Fp[NN][65];

    for (int idx = tid; idx < KK * NN; idx += 256) {
        int k = idx / NN, n = idx % NN;
        int h = ph * 8 + (n >> 3), w = pw * 8 + (n & 7);
        lg[k][n] = I[(((size_t)b * KK + k) * HH + h) * WW + w];
    }
    if (tid < KK) bc[tid] = R[((size_t)b * KK + tid) * PP + p];
    __syncthreads();

    if (tid < KK) {
        float mx = -1e30f;
        for (int n = 0; n < NN; n++) mx = fmaxf(mx, lg[tid][n]);
        float s = 0.f;
        for (int n = 0; n < NN; n++) { float e = __expf(lg[tid][n] - mx); pix[n][tid] = e; s += e; }
        float inv = 1.f / s;
        for (int n = 0; n < NN; n++) pix[n][tid] *= inv;
    }
    __syncthreads();

    for (int c0 = 0; c0 < CC; c0 += 64) {
        for (int idx = tid; idx < NN * 64; idx += 256) {
            int n = idx >> 6, cc = idx & 63;
            int h = ph * 8 + (n >> 3), w = pw * 8 + (n & 7);
            Fp[n][cc] = g_Fnhwc[((size_t)b * HW + h * WW + w) * CC + c0 + cc];
        }
        __syncthreads();
        for (int o = tid; o < KK * 64; o += 256) {
            int k = o >> 6, cc = o & 63;
            float acc = 0.f;
            #pragma unroll 8
            for (int n = 0; n < NN; n++) acc += pix[n][k] * Fp[n][cc];
            g_Fl[((size_t)bp * KK + k) * CC + c0 + cc] = acc * bc[k];
        }
        __syncthreads();
    }
}

// ---------------- kernel B: h = relu(lg_w1 @p F_l + F_l) ----------------
__global__ void k_lg1(const float* __restrict__ lg_w1) {
    int c0 = blockIdx.x * 64;
    int bk = blockIdx.y;
    int b = bk / KK, k = bk % KK;
    int tid = threadIdx.x;
    __shared__ float w1[64][64];
    __shared__ float Fl[64][65];
    for (int idx = tid; idx < 4096; idx += 256) w1[idx >> 6][idx & 63] = lg_w1[idx];
    for (int idx = tid; idx < 4096; idx += 256) {
        int p = idx >> 6, cc = idx & 63;
        Fl[p][cc] = g_Fl[(((size_t)b * PP + p) * KK + k) * CC + c0 + cc];
    }
    __syncthreads();
    for (int o = tid; o < 4096; o += 256) {
        int q = o >> 6, cc = o & 63;
        float acc = Fl[q][cc];
        #pragma unroll 8
        for (int p = 0; p < 64; p++) acc += w1[q][p] * Fl[p][cc];
        g_h[(((size_t)b * PP + q) * KK + k) * CC + c0 + cc] = fmaxf(acc, 0.f);
    }
}

// ---------------- generic GEMM: C[M,N] = epi(A[M,K] @ Bw[N,K]^T) ----------------
// MODE 0: plain  MODE 1: +bias[n]  MODE 2: resid[m,n] + relu(acc*scale[n] + bnb[n])
template <int MODE>
__global__ void k_gemm(const float* __restrict__ A, const float* __restrict__ Bw,
                       float* __restrict__ C, int M, int N, int K,
                       const float* __restrict__ bias,
                       const float* __restrict__ bng, const float* __restrict__ bnb,
                       const float* __restrict__ resid) {
    __shared__ float As[16][65];
    __shared__ float Bs[16][68];
    int m0 = blockIdx.y * 64, n0 = blockIdx.x * 64;
    int tid = threadIdx.x;
    int tx = tid & 15, ty = tid >> 4;
    float acc[4][4] = {};

    for (int k0 = 0; k0 < K; k0 += 16) {
        for (int idx = tid; idx < 64 * 16; idx += 256) {
            int i = idx >> 4, kk = idx & 15;
            int m = m0 + i;
            As[kk][i] = (m < M) ? A[(size_t)m * K + k0 + kk] : 0.f;
        }
        for (int idx = tid; idx < 64 * 16; idx += 256) {
            int j = idx >> 4, kk = idx & 15;
            Bs[kk][j] = Bw[(size_t)(n0 + j) * K + k0 + kk];
        }
        __syncthreads();
        #pragma unroll
        for (int kk = 0; kk < 16; kk++) {
            float a[4], bv[4];
            #pragma unroll
            for (int i = 0; i < 4; i++) a[i] = As[kk][ty * 4 + i];
            #pragma unroll
            for (int j = 0; j < 4; j++) bv[j] = Bs[kk][tx * 4 + j];
            #pragma unroll
            for (int i = 0; i < 4; i++)
                #pragma unroll
                for (int j = 0; j < 4; j++) acc[i][j] += a[i] * bv[j];
        }
        __syncthreads();
    }

    #pragma unroll
    for (int i = 0; i < 4; i++) {
        int m = m0 + ty * 4 + i;
        if (m >= M) continue;
        #pragma unroll
        for (int j = 0; j < 4; j++) {
            int n = n0 + tx * 4 + j;
            float v = acc[i][j];
            if (MODE == 1) v += bias[n];
            if (MODE == 2) {
                float s = bng[n] * rsqrtf(1.f + EPS);
                v = resid[(size_t)m * N + n] + fmaxf(v * s + bnb[n], 0.f);
            }
            C[(size_t)m * N + n] = v;
        }
    }
}

// ---------------- fuse: F_g[b,k,c] = sum_p fuse_w[p]*F_l2 + fuse_b ----------------
__global__ void k_fuse(const float* __restrict__ fuse_w, const float* __restrict__ fuse_b) {
    int bk = blockIdx.x;
    int b = bk / KK, k = bk % KK;
    int c = threadIdx.x;
    float acc = fuse_b[0];
    #pragma unroll 8
    for (int p = 0; p < PP; p++)
        acc += fuse_w[p] * g_Fl2[(((size_t)b * PP + p) * KK + k) * CC + c];
    g_Fg[(size_t)bk * CC + c] = acc;
}

// ---------------- attention per (b,p): softmax_k(q.k) @ v -> F_s (NHWC) ----------------
__global__ void k_attn() {
    int bp = blockIdx.x;
    int b = bp >> 6, p = bp & 63;
    int ph = p >> 3, pw = p & 7;
    int tid = threadIdx.x;
    __shared__ float ks[KK][DD];
    __shared__ float vs[KK][DD];
    for (int idx = tid; idx < KK * DD; idx += 256)
        ((float*)ks)[idx] = g_key[(size_t)bp * KK * DD + idx];
    for (int idx = tid; idx < KK * DD; idx += 256)
        ((float*)vs)[idx] = g_value[(size_t)b * KK * DD + idx];
    __syncthreads();

    int warp = tid >> 5, lane = tid & 31;
    for (int n = warp; n < NN; n += 8) {
        int h = ph * 8 + (n >> 3), w = pw * 8 + (n & 7);
        const float* qrow = &g_query[((size_t)b * HW + h * WW + w) * DD];
        float qr[8];
        #pragma unroll
        for (int i = 0; i < 8; i++) qr[i] = qrow[i * 32 + lane];

        float acc[KK];
        #pragma unroll
        for (int k = 0; k < KK; k++) acc[k] = 0.f;
        #pragma unroll
        for (int i = 0; i < 8; i++) {
            float qd = qr[i];
            #pragma unroll
            for (int k = 0; k < KK; k++) acc[k] += qd * ks[k][i * 32 + lane];
        }
        #pragma unroll
        for (int k = 0; k < KK; k++) {
            #pragma unroll
            for (int off = 16; off > 0; off >>= 1)
                acc[k] += __shfl_xor_sync(0xFFFFFFFFu, acc[k], off);
        }
        // softmax over k (replicated in all lanes)
        float mx = -1e30f;
        #pragma unroll
        for (int k = 0; k < KK; k++) mx = fmaxf(mx, acc[k]);
        float sum = 0.f;
        #pragma unroll
        for (int k = 0; k < KK; k++) { acc[k] = __expf(acc[k] - mx); sum += acc[k]; }
        float inv = 1.f / sum;
        #pragma unroll
        for (int k = 0; k < KK; k++) acc[k] *= inv;

        float* orow = &g_Fs[((size_t)b * HW + h * WW + w) * DD];
        #pragma unroll
        for (int i = 0; i < 8; i++) {
            int d = i * 32 + lane;
            float o = 0.f;
            #pragma unroll
            for (int k = 0; k < KK; k++) o += acc[k] * vs[k][d];
            orow[d] = o;
        }
    }
}

// ---------------- implicit-GEMM 3x3 conv, NHWC, pad=1, + BN(scale)+ReLU ----------------
// block: one (b,h) full output row (64 pixels) x 128 out channels
__global__ void k_conv3x3(const float* __restrict__ in, int Cin,
                          const float* __restrict__ wgt,
                          const float* __restrict__ bng, const float* __restrict__ bnb,
                          float* __restrict__ out, int out_stride) {
    const int BK = 16, BN = 128;
    __shared__ float As[BK][67];
    __shared__ float Ws[3][BK][BN];
    int h = blockIdx.x;
    int b = blockIdx.y;
    int n0 = blockIdx.z * BN;
    int tid = threadIdx.x;
    int tx = tid & 15;  // out-channel group: tx*8
    int ty = tid >> 4;  // pixel group: ty*4
    float acc[4][8] = {};

    for (int ky = 0; ky < 3; ky++) {
        int hin = h + ky - 1;
        if (hin < 0 || hin >= HH) continue;
        const float* inrow = in + ((size_t)(b * HH + hin) * WW) * Cin;
        for (int c0 = 0; c0 < Cin; c0 += BK) {
            for (int idx = tid; idx < 66 * BK; idx += 256) {
                int wq = idx / BK, ck = idx % BK;
                int wi = wq - 1;
                As[ck][wq] = (wi >= 0 && wi < WW) ? inrow[(size_t)wi * Cin + c0 + ck] : 0.f;
            }
            for (int idx = tid; idx < BN * BK * 3; idx += 256) {
                int cn = idx / (BK * 3);
                int r = idx % (BK * 3);
                int ck = r / 3, kx = r % 3;
                Ws[kx][ck][cn] = wgt[((size_t)(n0 + cn) * Cin + c0 + ck) * 9 + ky * 3 + kx];
            }
            __syncthreads();
            #pragma unroll 4
            for (int ck = 0; ck < BK; ck++) {
                float a[6];
                #pragma unroll
                for (int u = 0; u < 6; u++) a[u] = As[ck][ty * 4 + u];
                #pragma unroll
                for (int kx = 0; kx < 3; kx++) {
                    float wv[8];
                    #pragma unroll
                    for (int j = 0; j < 8; j++) wv[j] = Ws[kx][ck][tx * 8 + j];
                    #pragma unroll
                    for (int i = 0; i < 4; i++)
                        #pragma unroll
                        for (int j = 0; j < 8; j++) acc[i][j] += a[i + kx] * wv[j];
                }
            }
            __syncthreads();
        }
    }

    float s[8], bb[8];
    #pragma unroll
    for (int j = 0; j < 8; j++) {
        int n = n0 + tx * 8 + j;
        s[j] = bng[n] * rsqrtf(1.f + EPS);
        bb[j] = bnb[n];
    }
    #pragma unroll
    for (int i = 0; i < 4; i++) {
        int row = (b * HH + h) * WW + ty * 4 + i;
        #pragma unroll
        for (int j = 0; j < 8; j++)
            out[(size_t)row * out_stride + n0 + tx * 8 + j] = fmaxf(acc[i][j] * s[j] + bb[j], 0.f);
    }
}

// ---------------- final 1x1 classifier: out NCHW (B,19,64,64) ----------------
__global__ void k_classifier(const float* __restrict__ drop_w, float* __restrict__ out) {
    __shared__ float Xs[32][65];
    __shared__ float Ws[KK][33];
    int tid = threadIdx.x;
    int row0 = blockIdx.x * 64;
    int b = row0 >> 12;
    int hw0 = row0 & 4095;
    float acc[5] = {0.f, 0.f, 0.f, 0.f, 0.f};

    for (int c0 = 0; c0 < CC; c0 += 32) {
        for (int idx = tid; idx < 64 * 32; idx += 256) {
            int r = idx >> 5, cc = idx & 31;
            Xs[cc][r] = g_x3[(size_t)(row0 + r) * CC + c0 + cc];
        }
        for (int idx = tid; idx < KK * 32; idx += 256) {
            int k = idx >> 5, cc = idx & 31;
            Ws[k][cc] = drop_w[(size_t)k * CC + c0 + cc];
        }
        __syncthreads();
        #pragma unroll
        for (int sIdx = 0; sIdx < 5; sIdx++) {
            int o = tid + sIdx * 256;
            if (o < KK * 64) {
                int k = o >> 6, r = o & 63;
                float a = acc[sIdx];
                #pragma unroll 8
                for (int cc = 0; cc < 32; cc++) a += Ws[k][cc] * Xs[cc][r];
                acc[sIdx] = a;
            }
        }
        __syncthreads();
    }
    #pragma unroll
    for (int sIdx = 0; sIdx < 5; sIdx++) {
        int o = tid + sIdx * 256;
        if (o < KK * 64) {
            int k = o >> 6, r = o & 63;
            out[((size_t)b * KK + k) * HW + hw0 + r] = acc[sIdx];
        }
    }
}

// ---------------- launch ----------------
extern "C" void kernel_launch(void* const* d_in, const int* in_sizes, int n_in,
                              void* d_out, int out_size) {
    const float* M_1   = (const float*)d_in[0];
    const float* F     = (const float*)d_in[1];
    const float* I     = (const float*)d_in[2];
    const float* R     = (const float*)d_in[3];
    const float* lg_w1 = (const float*)d_in[4];
    const float* lg_w2 = (const float*)d_in[5];
    const float* fuse_w= (const float*)d_in[6];
    const float* fuse_b= (const float*)d_in[7];
    const float* q_w   = (const float*)d_in[8];
    const float* q_b   = (const float*)d_in[9];
    const float* k_w   = (const float*)d_in[10];
    const float* k_b   = (const float*)d_in[11];
    const float* v_w   = (const float*)d_in[12];
    const float* v_b   = (const float*)d_in[13];
    const float* c1_w  = (const float*)d_in[14];
    const float* bn1_g = (const float*)d_in[15];
    const float* bn1_b = (const float*)d_in[16];
    const float* c2_w  = (const float*)d_in[17];
    const float* bn2_g = (const float*)d_in[18];
    const float* bn2_b = (const float*)d_in[19];
    const float* c3_w  = (const float*)d_in[20];
    const float* bn3_g = (const float*)d_in[21];
    const float* bn3_b = (const float*)d_in[22];
    const float* drop_w= (const float*)d_in[23];
    float* out = (float*)d_out;

    float *p_Fnhwc, *p_cat, *p_Fl, *p_h, *p_Fl2, *p_Fg, *p_q, *p_k, *p_v, *p_Fs, *p_Fo1, *p_x3;
    cudaGetSymbolAddress((void**)&p_Fnhwc, g_Fnhwc);
    cudaGetSymbolAddress((void**)&p_cat,   g_cat);
    cudaGetSymbolAddress((void**)&p_Fl,    g_Fl);
    cudaGetSymbolAddress((void**)&p_h,     g_h);
    cudaGetSymbolAddress((void**)&p_Fl2,   g_Fl2);
    cudaGetSymbolAddress((void**)&p_Fg,    g_Fg);
    cudaGetSymbolAddress((void**)&p_q,     g_query);
    cudaGetSymbolAddress((void**)&p_k,     g_key);
    cudaGetSymbolAddress((void**)&p_v,     g_value);
    cudaGetSymbolAddress((void**)&p_Fs,    g_Fs);
    cudaGetSymbolAddress((void**)&p_Fo1,   g_Fo1);
    cudaGetSymbolAddress((void**)&p_x3,    g_x3);

    dim3 blk32(32, 8);

    // 1) F: NCHW -> NHWC
    k_transpose<<<dim3(HW / 32, CC / 32, BATCH), blk32>>>(F, p_Fnhwc, CC, CC, 0);
    // 2) M_1: NCHW -> NHWC into cat cols [512, 2560)
    k_transpose<<<dim3(HW / 32, 2048 / 32, BATCH), blk32>>>(M_1, p_cat, 2048, CIN3, CC);
    // 3) patch softmax + F_l
    k_patch_fl<<<BATCH * PP, 256>>>(I, R);
    // 4) LG part 1
    k_lg1<<<dim3(CC / 64, BATCH * KK), 256>>>(lg_w1);
    // 5) F_l2 = h @ lg_w2^T   (M=4864, N=512, K=512)
    k_gemm<0><<<dim3(CC / 64, (BATCH * PP * KK) / 64), 256>>>(
        p_h, lg_w2, p_Fl2, BATCH * PP * KK, CC, CC, nullptr, nullptr, nullptr, nullptr);
    // 6) fuse -> F_g
    k_fuse<<<BATCH * KK, CC>>>(fuse_w, fuse_b);
    // 7) query = F_nhwc @ q_w^T + q_b  (M=16384, N=256, K=512)
    k_gemm<1><<<dim3(DD / 64, (BATCH * HW) / 64), 256>>>(
        p_Fnhwc, q_w, p_q, BATCH * HW, DD, CC, q_b, nullptr, nullptr, nullptr);
    // 8) key = F_l2 @ k_w^T + k_b  (M=4864, N=256, K=512)
    k_gemm<1><<<dim3(DD / 64, (BATCH * PP * KK) / 64), 256>>>(
        p_Fl2, k_w, p_k, BATCH * PP * KK, DD, CC, k_b, nullptr, nullptr, nullptr);
    // 9) value = F_g @ v_w^T + v_b  (M=76, N=256, K=512)
    k_gemm<1><<<dim3(DD / 64, (BATCH * KK + 63) / 64), 256>>>(
        p_Fg, v_w, p_v, BATCH * KK, DD, CC, v_b, nullptr, nullptr, nullptr);
    // 10) attention -> F_s (NHWC)
    k_attn<<<BATCH * PP, 256>>>();
    // 11) Fo1 = F + relu(bn1(F_s @ c1_w^T))  (M=16384, N=512, K=256)
    k_gemm<2><<<dim3(CC / 64, (BATCH * HW) / 64), 256>>>(
        p_Fs, c1_w, p_Fo1, BATCH * HW, CC, DD, nullptr, bn1_g, bn1_b, p_Fnhwc);
    // 12) x2 = relu(bn2(conv3x3(Fo1)))  -> cat cols [0,512)
    k_conv3x3<<<dim3(HH, BATCH, CC / 128), 256>>>(p_Fo1, CC, c2_w, bn2_g, bn2_b, p_cat, CIN3);
    // 13) x3 = relu(bn3(conv3x3(cat)))
    k_conv3x3<<<dim3(HH, BATCH, CC / 128), 256>>>(p_cat, CIN3, c3_w, bn3_g, bn3_b, p_x3, CC);
    // 14) final classifier, NCHW output
    k_classifier<<<(BATCH * HW) / 64, 256>>>(drop_w, out);
}

// round 2
// speedup vs baseline: 1.4581x; 1.4581x over previous
#include <cuda_runtime.h>
#include <cuda_bf16.h>
#include <mma.h>
#include <math.h>

using namespace nvcuda;
typedef __nv_bfloat16 bf16;

#define EPS 1e-5f

// Problem constants
#define BATCH 4
#define HH 64
#define WW 64
#define HW 4096
#define CC 512
#define KK 19
#define PP 64
#define NN 64
#define DD 256
#define CIN3 2560

// ---------------- scratch (static device memory) ----------------
__device__ float g_Fnhwc[BATCH * HW * CC];
__device__ float g_Fl[BATCH * PP * KK * CC];
__device__ float g_h[BATCH * PP * KK * CC];
__device__ float g_Fl2[BATCH * PP * KK * CC];
__device__ float g_Fg[BATCH * KK * CC];
__device__ float g_query[BATCH * HW * DD];
__device__ float g_key[BATCH * PP * KK * DD];
__device__ float g_value[BATCH * KK * DD];
__device__ float g_Fs[BATCH * HW * DD];
__device__ float g_x3[BATCH * HW * CC];

// bf16 split pairs
__device__ bf16 g_cath[(size_t)BATCH * HW * CIN3];   // cols [0,512)=x2, [512,2560)=M1
__device__ bf16 g_catl[(size_t)BATCH * HW * CIN3];
__device__ bf16 g_Fo1h[BATCH * HW * CC];
__device__ bf16 g_Fo1l[BATCH * HW * CC];
__device__ bf16 g_w2h[512 * 512 * 9];
__device__ bf16 g_w2l[512 * 512 * 9];
__device__ bf16 g_w3h[512 * 2560 * 9];
__device__ bf16 g_w3l[512 * 2560 * 9];

__device__ __forceinline__ void split_bf16(float v, bf16& hi, bf16& lo) {
    hi = __float2bfloat16(v);
    lo = __float2bfloat16(v - __bfloat162float(hi));
}

// ---------------- transpose NCHW -> NHWC (fp32 out) ----------------
__global__ void k_transpose(const float* __restrict__ in, float* __restrict__ out,
                            int C, int out_stride, int col_off) {
    __shared__ float tile[32][33];
    int b = blockIdx.z;
    int hw0 = blockIdx.x * 32, c0 = blockIdx.y * 32;
    int tx = threadIdx.x, ty = threadIdx.y;
    for (int i = ty; i < 32; i += 8)
        tile[i][tx] = in[((size_t)b * C + c0 + i) * HW + hw0 + tx];
    __syncthreads();
    for (int i = ty; i < 32; i += 8)
        out[((size_t)b * HW + hw0 + i) * out_stride + col_off + c0 + tx] = tile[tx][i];
}

// ---------------- transpose NCHW -> NHWC (bf16 hi/lo out) ----------------
__global__ void k_transpose_pair(const float* __restrict__ in, bf16* __restrict__ oh,
                                 bf16* __restrict__ ol, int C, int out_stride, int col_off) {
    __shared__ float tile[32][33];
    int b = blockIdx.z;
    int hw0 = blockIdx.x * 32, c0 = blockIdx.y * 32;
    int tx = threadIdx.x, ty = threadIdx.y;
    for (int i = ty; i < 32; i += 8)
        tile[i][tx] = in[((size_t)b * C + c0 + i) * HW + hw0 + tx];
    __syncthreads();
    for (int i = ty; i < 32; i += 8) {
        float v = tile[tx][i];
        bf16 hi, lo; split_bf16(v, hi, lo);
        size_t o = ((size_t)b * HW + hw0 + i) * out_stride + col_off + c0 + tx;
        oh[o] = hi; ol[o] = lo;
    }
}

// ---------------- weight split + relayout: OIHW -> [(ky*3+kx)][Cin][OutC] ----------------
__global__ void k_wsplit(const float* __restrict__ w, bf16* __restrict__ oh,
                         bf16* __restrict__ ol, int OutC, int Cin) {
    size_t idx = (size_t)blockIdx.x * 256 + threadIdx.x;
    size_t total = (size_t)OutC * Cin * 9;
    if (idx >= total) return;
    int o = idx / (Cin * 9);
    int r = idx % (Cin * 9);
    int i = r / 9, kq = r % 9;
    float v = w[idx];
    bf16 hi, lo; split_bf16(v, hi, lo);
    size_t dst = ((size_t)kq * Cin + i) * OutC + o;
    oh[dst] = hi; ol[dst] = lo;
}

// ---------------- kernel A: patch softmax + F_l ----------------
__global__ void k_patch_fl(const float* __restrict__ I, const float* __restrict__ R) {
    int bp = blockIdx.x;
    int b = bp >> 6, p = bp & 63;
    int ph = p >> 3, pw = p & 7;
    int tid = threadIdx.x;

    __shared__ float lg[KK][NN];
    __shared__ float pix[NN][20];
    __shared__ float bc[KK];
    __shared__ float Fp[NN][65];

    for (int idx = tid; idx < KK * NN; idx += 256) {
        int k = idx / NN, n = idx % NN;
        int h = ph * 8 + (n >> 3), w = pw * 8 + (n & 7);
        lg[k][n] = I[(((size_t)b * KK + k) * HH + h) * WW + w];
    }
    if (tid < KK) bc[tid] = R[((size_t)b * KK + tid) * PP + p];
    __syncthreads();

    if (tid < KK) {
        float mx = -1e30f;
        for (int n = 0; n < NN; n++) mx = fmaxf(mx, lg[tid][n]);
        float s = 0.f;
        for (int n = 0; n < NN; n++) { float e = __expf(lg[tid][n] - mx); pix[n][tid] = e; s += e; }
        float inv = 1.f / s;
        for (int n = 0; n < NN; n++) pix[n][tid] *= inv;
    }
    __syncthreads();

    for (int c0 = 0; c0 < CC; c0 += 64) {
        for (int idx = tid; idx < NN * 64; idx += 256) {
            int n = idx >> 6, cc = idx & 63;
            int h = ph * 8 + (n >> 3), w = pw * 8 + (n & 7);
            Fp[n][cc] = g_Fnhwc[((size_t)b * HW + h * WW + w) * CC + c0 + cc];
        }
        __syncthreads();
        for (int o = tid; o < KK * 64; o += 256) {
            int k = o >> 6, cc = o & 63;
            float acc = 0.f;
            #pragma unroll 8
            for (int n = 0; n < NN; n++) acc += pix[n][k] * Fp[n][cc];
            g_Fl[((size_t)bp * KK + k) * CC + c0 + cc] = acc * bc[k];
        }
        __syncthreads();
    }
}

// ---------------- kernel B: h = relu(lg_w1 @p F_l + F_l) ----------------
__global__ void k_lg1(const float* __restrict__ lg_w1) {
    int c0 = blockIdx.x * 64;
    int bk = blockIdx.y;
    int b = bk / KK, k = bk % KK;
    int tid = threadIdx.x;
    __shared__ float w1[64][64];
    __shared__ float Fl[64][65];
    for (int idx = tid; idx < 4096; idx += 256) w1[idx >> 6][idx & 63] = lg_w1[idx];
    for (int idx = tid; idx < 4096; idx += 256) {
        int p = idx >> 6, cc = idx & 63;
        Fl[p][cc] = g_Fl[(((size_t)b * PP + p) * KK + k) * CC + c0 + cc];
    }
    __syncthreads();
    for (int o = tid; o < 4096; o += 256) {
        int q = o >> 6, cc = o & 63;
        float acc = Fl[q][cc];
        #pragma unroll 8
        for (int p = 0; p < 64; p++) acc += w1[q][p] * Fl[p][cc];
        g_h[(((size_t)b * PP + q) * KK + k) * CC + c0 + cc] = fmaxf(acc, 0.f);
    }
}

// ---------------- generic GEMM: C = epi(A[M,K] @ Bw[N,K]^T) ----------------
// MODE 0: plain  MODE 1: +bias  MODE 2: (resid + relu(acc*scale + bnb)) -> bf16 hi/lo
template <int MODE>
__global__ void k_gemm(const float* __restrict__ A, const float* __restrict__ Bw,
                       float* __restrict__ C, int M, int N, int K,
                       const float* __restrict__ bias,
                       const float* __restrict__ bng, const float* __restrict__ bnb,
                       const float* __restrict__ resid,
                       bf16* __restrict__ Ch, bf16* __restrict__ Cl) {
    __shared__ float As[16][65];
    __shared__ float Bs[16][68];
    int m0 = blockIdx.y * 64, n0 = blockIdx.x * 64;
    int tid = threadIdx.x;
    int tx = tid & 15, ty = tid >> 4;
    float acc[4][4] = {};

    for (int k0 = 0; k0 < K; k0 += 16) {
        for (int idx = tid; idx < 64 * 16; idx += 256) {
            int i = idx >> 4, kk = idx & 15;
            int m = m0 + i;
            As[kk][i] = (m < M) ? A[(size_t)m * K + k0 + kk] : 0.f;
        }
        for (int idx = tid; idx < 64 * 16; idx += 256) {
            int j = idx >> 4, kk = idx & 15;
            Bs[kk][j] = Bw[(size_t)(n0 + j) * K + k0 + kk];
        }
        __syncthreads();
        #pragma unroll
        for (int kk = 0; kk < 16; kk++) {
            float a[4], bv[4];
            #pragma unroll
            for (int i = 0; i < 4; i++) a[i] = As[kk][ty * 4 + i];
            #pragma unroll
            for (int j = 0; j < 4; j++) bv[j] = Bs[kk][tx * 4 + j];
            #pragma unroll
            for (int i = 0; i < 4; i++)
                #pragma unroll
                for (int j = 0; j < 4; j++) acc[i][j] += a[i] * bv[j];
        }
        __syncthreads();
    }

    #pragma unroll
    for (int i = 0; i < 4; i++) {
        int m = m0 + ty * 4 + i;
        if (m >= M) continue;
        #pragma unroll
        for (int j = 0; j < 4; j++) {
            int n = n0 + tx * 4 + j;
            float v = acc[i][j];
            if (MODE == 1) v += bias[n];
            if (MODE == 2) {
                float s = bng[n] * rsqrtf(1.f + EPS);
                v = resid[(size_t)m * N + n] + fmaxf(v * s + bnb[n], 0.f);
                bf16 hi, lo; split_bf16(v, hi, lo);
                Ch[(size_t)m * N + n] = hi;
                Cl[(size_t)m * N + n] = lo;
            } else {
                C[(size_t)m * N + n] = v;
            }
        }
    }
}

// ---------------- fuse ----------------
__global__ void k_fuse(const float* __restrict__ fuse_w, const float* __restrict__ fuse_b) {
    int bk = blockIdx.x;
    int c = threadIdx.x;
    int b = bk / KK, k = bk % KK;
    float acc = fuse_b[0];
    #pragma unroll 8
    for (int p = 0; p < PP; p++)
        acc += fuse_w[p] * g_Fl2[(((size_t)b * PP + p) * KK + k) * CC + c];
    g_Fg[(size_t)bk * CC + c] = acc;
}

// ---------------- attention ----------------
__global__ void k_attn() {
    int bp = blockIdx.x;
    int b = bp >> 6, p = bp & 63;
    int ph = p >> 3, pw = p & 7;
    int tid = threadIdx.x;
    __shared__ float ks[KK][DD];
    __shared__ float vs[KK][DD];
    for (int idx = tid; idx < KK * DD; idx += 256)
        ((float*)ks)[idx] = g_key[(size_t)bp * KK * DD + idx];
    for (int idx = tid; idx < KK * DD; idx += 256)
        ((float*)vs)[idx] = g_value[(size_t)b * KK * DD + idx];
    __syncthreads();

    int warp = tid >> 5, lane = tid & 31;
    for (int n = warp; n < NN; n += 8) {
        int h = ph * 8 + (n >> 3), w = pw * 8 + (n & 7);
        const float* qrow = &g_query[((size_t)b * HW + h * WW + w) * DD];
        float qr[8];
        #pragma unroll
        for (int i = 0; i < 8; i++) qr[i] = qrow[i * 32 + lane];

        float acc[KK];
        #pragma unroll
        for (int k = 0; k < KK; k++) acc[k] = 0.f;
        #pragma unroll
        for (int i = 0; i < 8; i++) {
            float qd = qr[i];
            #pragma unroll
            for (int k = 0; k < KK; k++) acc[k] += qd * ks[k][i * 32 + lane];
        }
        #pragma unroll
        for (int k = 0; k < KK; k++) {
            #pragma unroll
            for (int off = 16; off > 0; off >>= 1)
                acc[k] += __shfl_xor_sync(0xFFFFFFFFu, acc[k], off);
        }
        float mx = -1e30f;
        #pragma unroll
        for (int k = 0; k < KK; k++) mx = fmaxf(mx, acc[k]);
        float sum = 0.f;
        #pragma unroll
        for (int k = 0; k < KK; k++) { acc[k] = __expf(acc[k] - mx); sum += acc[k]; }
        float inv = 1.f / sum;
        #pragma unroll
        for (int k = 0; k < KK; k++) acc[k] *= inv;

        float* orow = &g_Fs[((size_t)b * HW + h * WW + w) * DD];
        #pragma unroll
        for (int i = 0; i < 8; i++) {
            int d = i * 32 + lane;
            float o = 0.f;
            #pragma unroll
            for (int k = 0; k < KK; k++) o += acc[k] * vs[k][d];
            orow[d] = o;
        }
    }
}

// ---------------- tensor-core 3x3 conv, NHWC, pad=1, split-bf16, + BN+ReLU ----------------
// block: one output row (64 px) x 128 outch. 8 warps: warpM in [0,4) x warpN in [0,2).
// smem: Wh[3][16][128] | Wl | Ah[66][16] | Al ; epilogue reuses base as float[64][132]
__global__ void k_conv_mma(const bf16* __restrict__ in_hi, const bf16* __restrict__ in_lo,
                           int Cin,
                           const bf16* __restrict__ w_hi, const bf16* __restrict__ w_lo,
                           int OutC,
                           const float* __restrict__ bng, const float* __restrict__ bnb,
                           float* __restrict__ out_f,
                           bf16* __restrict__ out_hi, bf16* __restrict__ out_lo,
                           int out_stride) {
    extern __shared__ char smem[];
    bf16* Wh = (bf16*)smem;                   // 3*16*128 = 6144 elems
    bf16* Wl = (bf16*)(smem + 12288);
    bf16* Ah = (bf16*)(smem + 24576);         // 66*16 = 1056 elems
    bf16* Al = (bf16*)(smem + 26688);

    int h = blockIdx.x, b = blockIdx.y, n0 = blockIdx.z * 128;
    int tid = threadIdx.x;
    int warp = tid >> 5;
    int warpM = warp >> 1, warpN = warp & 1;

    wmma::fragment<wmma::accumulator, 16, 16, 16, float> acc[4];
    #pragma unroll
    for (int j = 0; j < 4; j++) wmma::fill_fragment(acc[j], 0.f);

    for (int ky = 0; ky < 3; ky++) {
        int hin = h + ky - 1;
        if (hin < 0 || hin >= HH) continue;
        const bf16* rowh = in_hi + ((size_t)(b * HH + hin) * WW) * Cin;
        const bf16* rowl = in_lo + ((size_t)(b * HH + hin) * WW) * Cin;
        const bf16* wbh = w_hi + (size_t)(ky * 3) * Cin * OutC;
        const bf16* wbl = w_lo + (size_t)(ky * 3) * Cin * OutC;

        for (int c0 = 0; c0 < Cin; c0 += 16) {
            // A tile: 66 px x 16 ch
            for (int idx = tid; idx < 66 * 16; idx += 256) {
                int wi = idx >> 4, c = idx & 15;
                int gw = wi - 1;
                bool v = (gw >= 0 && gw < WW);
                Ah[idx] = v ? rowh[(size_t)gw * Cin + c0 + c] : __float2bfloat16(0.f);
                Al[idx] = v ? rowl[(size_t)gw * Cin + c0 + c] : __float2bfloat16(0.f);
            }
            // W tile: 3 kx x 16 ch x 128 outch
            for (int idx = tid; idx < 3 * 16 * 128; idx += 256) {
                int kx = idx >> 11;
                int r = idx & 2047;
                int c = r >> 7, o = r & 127;
                size_t g = ((size_t)kx * Cin + c0 + c) * OutC + n0 + o;
                Wh[idx] = wbh[g];
                Wl[idx] = wbl[g];
            }
            __syncthreads();

            #pragma unroll
            for (int kx = 0; kx < 3; kx++) {
                wmma::fragment<wmma::matrix_a, 16, 16, 16, bf16, wmma::row_major> ah, al;
                wmma::load_matrix_sync(ah, Ah + (warpM * 16 + kx) * 16, 16);
                wmma::load_matrix_sync(al, Al + (warpM * 16 + kx) * 16, 16);
                #pragma unroll
                for (int j = 0; j < 4; j++) {
                    wmma::fragment<wmma::matrix_b, 16, 16, 16, bf16, wmma::row_major> bh, bl;
                    int boff = kx * 2048 + warpN * 64 + j * 16;
                    wmma::load_matrix_sync(bh, Wh + boff, 128);
                    wmma::load_matrix_sync(bl, Wl + boff, 128);
                    wmma::mma_sync(acc[j], ah, bh, acc[j]);
                    wmma::mma_sync(acc[j], ah, bl, acc[j]);
                    wmma::mma_sync(acc[j], al, bh, acc[j]);
                }
            }
            __syncthreads();
        }
    }

    // epilogue via smem (reuse)
    float* So = (float*)smem;   // 64 x 132
    #pragma unroll
    for (int j = 0; j < 4; j++)
        wmma::store_matrix_sync(So + (warpM * 16) * 132 + warpN * 64 + j * 16,
                                acc[j], 132, wmma::mem_row_major);
    __syncthreads();

    int row_base = (b * HH + h) * WW;
    for (int idx = tid; idx < 64 * 128; idx += 256) {
        int m = idx >> 7, n = idx & 127;
        float v = So[m * 132 + n];
        int gn = n0 + n;
        float s = bng[gn] * rsqrtf(1.f + EPS);
        v = fmaxf(v * s + bnb[gn], 0.f);
        size_t o = (size_t)(row_base + m) * out_stride + gn;
        if (out_f) {
            out_f[o] = v;
        } else {
            bf16 hi, lo; split_bf16(v, hi, lo);
            out_hi[o] = hi; out_lo[o] = lo;
        }
    }
}

// ---------------- final 1x1 classifier -> NCHW ----------------
__global__ void k_classifier(const float* __restrict__ drop_w, float* __restrict__ out) {
    __shared__ float Xs[32][65];
    __shared__ float Ws[KK][33];
    int tid = threadIdx.x;
    int row0 = blockIdx.x * 64;
    int b = row0 >> 12;
    int hw0 = row0 & 4095;
    float acc[5] = {0.f, 0.f, 0.f, 0.f, 0.f};

    for (int c0 = 0; c0 < CC; c0 += 32) {
        for (int idx = tid; idx < 64 * 32; idx += 256) {
            int r = idx >> 5, cc = idx & 31;
            Xs[cc][r] = g_x3[(size_t)(row0 + r) * CC + c0 + cc];
        }
        for (int idx = tid; idx < KK * 32; idx += 256) {
            int k = idx >> 5, cc = idx & 31;
            Ws[k][cc] = drop_w[(size_t)k * CC + c0 + cc];
        }
        __syncthreads();
        #pragma unroll
        for (int sIdx = 0; sIdx < 5; sIdx++) {
            int o = tid + sIdx * 256;
            if (o < KK * 64) {
                int k = o >> 6, r = o & 63;
                float a = acc[sIdx];
                #pragma unroll 8
                for (int cc = 0; cc < 32; cc++) a += Ws[k][cc] * Xs[cc][r];
                acc[sIdx] = a;
            }
        }
        __syncthreads();
    }
    #pragma unroll
    for (int sIdx = 0; sIdx < 5; sIdx++) {
        int o = tid + sIdx * 256;
        if (o < KK * 64) {
            int k = o >> 6, r = o & 63;
            out[((size_t)b * KK + k) * HW + hw0 + r] = acc[sIdx];
        }
    }
}

// ---------------- launch ----------------
extern "C" void kernel_launch(void* const* d_in, const int* in_sizes, int n_in,
                              void* d_out, int out_size) {
    const float* M_1   = (const float*)d_in[0];
    const float* F     = (const float*)d_in[1];
    const float* I     = (const float*)d_in[2];
    const float* R     = (const float*)d_in[3];
    const float* lg_w1 = (const float*)d_in[4];
    const float* lg_w2 = (const float*)d_in[5];
    const float* fuse_w= (const float*)d_in[6];
    const float* fuse_b= (const float*)d_in[7];
    const float* q_w   = (const float*)d_in[8];
    const float* q_b   = (const float*)d_in[9];
    const float* k_w   = (const float*)d_in[10];
    const float* k_b   = (const float*)d_in[11];
    const float* v_w   = (const float*)d_in[12];
    const float* v_b   = (const float*)d_in[13];
    const float* c1_w  = (const float*)d_in[14];
    const float* bn1_g = (const float*)d_in[15];
    const float* bn1_b = (const float*)d_in[16];
    const float* c2_w  = (const float*)d_in[17];
    const float* bn2_g = (const float*)d_in[18];
    const float* bn2_b = (const float*)d_in[19];
    const float* c3_w  = (const float*)d_in[20];
    const float* bn3_g = (const float*)d_in[21];
    const float* bn3_b = (const float*)d_in[22];
    const float* drop_w= (const float*)d_in[23];
    float* out = (float*)d_out;

    float *p_Fnhwc, *p_Fl, *p_h, *p_Fl2, *p_Fg, *p_q, *p_k, *p_v, *p_Fs, *p_x3;
    bf16 *p_cath, *p_catl, *p_Fo1h, *p_Fo1l, *p_w2h, *p_w2l, *p_w3h, *p_w3l;
    cudaGetSymbolAddress((void**)&p_Fnhwc, g_Fnhwc);
    cudaGetSymbolAddress((void**)&p_Fl,    g_Fl);
    cudaGetSymbolAddress((void**)&p_h,     g_h);
    cudaGetSymbolAddress((void**)&p_Fl2,   g_Fl2);
    cudaGetSymbolAddress((void**)&p_Fg,    g_Fg);
    cudaGetSymbolAddress((void**)&p_q,     g_query);
    cudaGetSymbolAddress((void**)&p_k,     g_key);
    cudaGetSymbolAddress((void**)&p_v,     g_value);
    cudaGetSymbolAddress((void**)&p_Fs,    g_Fs);
    cudaGetSymbolAddress((void**)&p_x3,    g_x3);
    cudaGetSymbolAddress((void**)&p_cath,  g_cath);
    cudaGetSymbolAddress((void**)&p_catl,  g_catl);
    cudaGetSymbolAddress((void**)&p_Fo1h,  g_Fo1h);
    cudaGetSymbolAddress((void**)&p_Fo1l,  g_Fo1l);
    cudaGetSymbolAddress((void**)&p_w2h,   g_w2h);
    cudaGetSymbolAddress((void**)&p_w2l,   g_w2l);
    cudaGetSymbolAddress((void**)&p_w3h,   g_w3h);
    cudaGetSymbolAddress((void**)&p_w3l,   g_w3l);

    dim3 blk32(32, 8);
    const int CONV_SMEM = 64 * 132 * 4;  // 33792 B (>= mainloop's 28800 B)

    // weight split/relayout (independent; early)
    k_wsplit<<<(512 * 512 * 9 + 255) / 256, 256>>>(c2_w, p_w2h, p_w2l, 512, 512);
    k_wsplit<<<(512 * 2560 * 9 + 255) / 256, 256>>>(c3_w, p_w3h, p_w3l, 512, 2560);

    // 1) F: NCHW -> NHWC (fp32)
    k_transpose<<<dim3(HW / 32, CC / 32, BATCH), blk32>>>(F, p_Fnhwc, CC, CC, 0);
    // 2) M_1: NCHW -> NHWC bf16 pair into cat cols [512,2560)
    k_transpose_pair<<<dim3(HW / 32, 2048 / 32, BATCH), blk32>>>(M_1, p_cath, p_catl, 2048, CIN3, CC);
    // 3) patch softmax + F_l
    k_patch_fl<<<BATCH * PP, 256>>>(I, R);
    // 4) LG part 1
    k_lg1<<<dim3(CC / 64, BATCH * KK), 256>>>(lg_w1);
    // 5) F_l2 = h @ lg_w2^T
    k_gemm<0><<<dim3(CC / 64, (BATCH * PP * KK) / 64), 256>>>(
        p_h, lg_w2, p_Fl2, BATCH * PP * KK, CC, CC, nullptr, nullptr, nullptr, nullptr, nullptr, nullptr);
    // 6) fuse
    k_fuse<<<BATCH * KK, CC>>>(fuse_w, fuse_b);
    // 7) query
    k_gemm<1><<<dim3(DD / 64, (BATCH * HW) / 64), 256>>>(
        p_Fnhwc, q_w, p_q, BATCH * HW, DD, CC, q_b, nullptr, nullptr, nullptr, nullptr, nullptr);
    // 8) key
    k_gemm<1><<<dim3(DD / 64, (BATCH * PP * KK) / 64), 256>>>(
        p_Fl2, k_w, p_k, BATCH * PP * KK, DD, CC, k_b, nullptr, nullptr, nullptr, nullptr, nullptr);
    // 9) value
    k_gemm<1><<<dim3(DD / 64, (BATCH * KK + 63) / 64), 256>>>(
        p_Fg, v_w, p_v, BATCH * KK, DD, CC, v_b, nullptr, nullptr, nullptr, nullptr, nullptr);
    // 10) attention
    k_attn<<<BATCH * PP, 256>>>();
    // 11) Fo1 = F + relu(bn1(F_s @ c1_w^T))  -> bf16 pair
    k_gemm<2><<<dim3(CC / 64, (BATCH * HW) / 64), 256>>>(
        p_Fs, c1_w, nullptr, BATCH * HW, CC, DD, nullptr, bn1_g, bn1_b, p_Fnhwc, p_Fo1h, p_Fo1l);
    // 12) x2 = relu(bn2(conv3x3(Fo1))) -> cat cols [0,512) bf16 pair
    k_conv_mma<<<dim3(HH, BATCH, 4), 256, CONV_SMEM>>>(
        p_Fo1h, p_Fo1l, CC, p_w2h, p_w2l, 512, bn2_g, bn2_b,
        nullptr, p_cath, p_catl, CIN3);
    // 13) x3 = relu(bn3(conv3x3(cat))) -> fp32
    k_conv_mma<<<dim3(HH, BATCH, 4), 256, CONV_SMEM>>>(
        p_cath, p_catl, CIN3, p_w3h, p_w3l, 512, bn3_g, bn3_b,
        p_x3, nullptr, nullptr, CC);
    // 14) classifier
    k_classifier<<<(BATCH * HW) / 64, 256>>>(drop_w, out);
}

// round 3
// speedup vs baseline: 2.3783x; 1.6311x over previous
#include <cuda_runtime.h>
#include <cuda_bf16.h>
#include <mma.h>
#include <math.h>

using namespace nvcuda;
typedef __nv_bfloat16 bf16;

#define EPS 1e-5f

#define BATCH 4
#define HH 64
#define WW 64
#define HW 4096
#define CC 512
#define KK 19
#define PP 64
#define NN 64
#define DD 256
#define CIN3 2560

// ---------------- scratch ----------------
__device__ float g_Fnhwc[BATCH * HW * CC];
__device__ float g_Fl[BATCH * PP * KK * CC];
__device__ float g_h[BATCH * PP * KK * CC];
__device__ float g_Fl2[BATCH * PP * KK * CC];
__device__ float g_Fg[BATCH * KK * CC];
__device__ float g_query[BATCH * HW * DD];
__device__ float g_key[BATCH * PP * KK * DD];
__device__ float g_value[BATCH * KK * DD];
__device__ float g_Fs[BATCH * HW * DD];
__device__ float g_x3[BATCH * HW * CC];

__device__ bf16 g_cath[(size_t)BATCH * HW * CIN3];
__device__ bf16 g_catl[(size_t)BATCH * HW * CIN3];
__device__ bf16 g_Fo1h[BATCH * HW * CC];
__device__ bf16 g_Fo1l[BATCH * HW * CC];
__device__ bf16 g_w2h[512 * 512 * 9];
__device__ bf16 g_w2l[512 * 512 * 9];
__device__ bf16 g_w3h[512 * 2560 * 9];
__device__ bf16 g_w3l[512 * 2560 * 9];

__device__ __forceinline__ void split_bf16(float v, bf16& hi, bf16& lo) {
    hi = __float2bfloat16(v);
    lo = __float2bfloat16(v - __bfloat162float(hi));
}

// ---------------- transpose NCHW -> NHWC (fp32) ----------------
__global__ void k_transpose(const float* __restrict__ in, float* __restrict__ out,
                            int C, int out_stride, int col_off) {
    __shared__ float tile[32][33];
    int b = blockIdx.z;
    int hw0 = blockIdx.x * 32, c0 = blockIdx.y * 32;
    int tx = threadIdx.x, ty = threadIdx.y;
    for (int i = ty; i < 32; i += 8)
        tile[i][tx] = in[((size_t)b * C + c0 + i) * HW + hw0 + tx];
    __syncthreads();
    for (int i = ty; i < 32; i += 8)
        out[((size_t)b * HW + hw0 + i) * out_stride + col_off + c0 + tx] = tile[tx][i];
}

// ---------------- transpose NCHW -> NHWC (bf16 hi/lo) ----------------
__global__ void k_transpose_pair(const float* __restrict__ in, bf16* __restrict__ oh,
                                 bf16* __restrict__ ol, int C, int out_stride, int col_off) {
    __shared__ float tile[32][33];
    int b = blockIdx.z;
    int hw0 = blockIdx.x * 32, c0 = blockIdx.y * 32;
    int tx = threadIdx.x, ty = threadIdx.y;
    for (int i = ty; i < 32; i += 8)
        tile[i][tx] = in[((size_t)b * C + c0 + i) * HW + hw0 + tx];
    __syncthreads();
    for (int i = ty; i < 32; i += 8) {
        float v = tile[tx][i];
        bf16 hi, lo; split_bf16(v, hi, lo);
        size_t o = ((size_t)b * HW + hw0 + i) * out_stride + col_off + c0 + tx;
        oh[o] = hi; ol[o] = lo;
    }
}

// ---------------- weight split + relayout: OIHW -> [(ky*3+kx)][Cin][OutC] ----------------
__global__ void k_wsplit(const float* __restrict__ w, bf16* __restrict__ oh,
                         bf16* __restrict__ ol, int OutC, int Cin) {
    size_t idx = (size_t)blockIdx.x * 256 + threadIdx.x;
    size_t total = (size_t)OutC * Cin * 9;
    if (idx >= total) return;
    int o = idx / (Cin * 9);
    int r = idx % (Cin * 9);
    int i = r / 9, kq = r % 9;
    float v = w[idx];
    bf16 hi, lo; split_bf16(v, hi, lo);
    size_t dst = ((size_t)kq * Cin + i) * OutC + o;
    oh[dst] = hi; ol[dst] = lo;
}

// ---------------- patch softmax + F_l ----------------
__global__ void k_patch_fl(const float* __restrict__ I, const float* __restrict__ R) {
    int bp = blockIdx.x;
    int b = bp >> 6, p = bp & 63;
    int ph = p >> 3, pw = p & 7;
    int tid = threadIdx.x;

    __shared__ float lg[KK][NN];
    __shared__ float pix[NN][20];
    __shared__ float bc[KK];
    __shared__ float Fp[NN][65];

    for (int idx = tid; idx < KK * NN; idx += 256) {
        int k = idx / NN, n = idx % NN;
        int h = ph * 8 + (n >> 3), w = pw * 8 + (n & 7);
        lg[k][n] = I[(((size_t)b * KK + k) * HH + h) * WW + w];
    }
    if (tid < KK) bc[tid] = R[((size_t)b * KK + tid) * PP + p];
    __syncthreads();

    if (tid < KK) {
        float mx = -1e30f;
        for (int n = 0; n < NN; n++) mx = fmaxf(mx, lg[tid][n]);
        float s = 0.f;
        for (int n = 0; n < NN; n++) { float e = __expf(lg[tid][n] - mx); pix[n][tid] = e; s += e; }
        float inv = 1.f / s;
        for (int n = 0; n < NN; n++) pix[n][tid] *= inv;
    }
    __syncthreads();

    for (int c0 = 0; c0 < CC; c0 += 64) {
        for (int idx = tid; idx < NN * 64; idx += 256) {
            int n = idx >> 6, cc = idx & 63;
            int h = ph * 8 + (n >> 3), w = pw * 8 + (n & 7);
            Fp[n][cc] = g_Fnhwc[((size_t)b * HW + h * WW + w) * CC + c0 + cc];
        }
        __syncthreads();
        for (int o = tid; o < KK * 64; o += 256) {
            int k = o >> 6, cc = o & 63;
            float acc = 0.f;
            #pragma unroll 8
            for (int n = 0; n < NN; n++) acc += pix[n][k] * Fp[n][cc];
            g_Fl[((size_t)bp * KK + k) * CC + c0 + cc] = acc * bc[k];
        }
        __syncthreads();
    }
}

// ---------------- h = relu(lg_w1 @p F_l + F_l) ----------------
__global__ void k_lg1(const float* __restrict__ lg_w1) {
    int c0 = blockIdx.x * 64;
    int bk = blockIdx.y;
    int b = bk / KK, k = bk % KK;
    int tid = threadIdx.x;
    __shared__ float w1[64][64];
    __shared__ float Fl[64][65];
    for (int idx = tid; idx < 4096; idx += 256) w1[idx >> 6][idx & 63] = lg_w1[idx];
    for (int idx = tid; idx < 4096; idx += 256) {
        int p = idx >> 6, cc = idx & 63;
        Fl[p][cc] = g_Fl[(((size_t)b * PP + p) * KK + k) * CC + c0 + cc];
    }
    __syncthreads();
    for (int o = tid; o < 4096; o += 256) {
        int q = o >> 6, cc = o & 63;
        float acc = Fl[q][cc];
        #pragma unroll 8
        for (int p = 0; p < 64; p++) acc += w1[q][p] * Fl[p][cc];
        g_h[(((size_t)b * PP + q) * KK + k) * CC + c0 + cc] = fmaxf(acc, 0.f);
    }
}

// ---------------- generic fp32 GEMM ----------------
template <int MODE>
__global__ void k_gemm(const float* __restrict__ A, const float* __restrict__ Bw,
                       float* __restrict__ C, int M, int N, int K,
                       const float* __restrict__ bias,
                       const float* __restrict__ bng, const float* __restrict__ bnb,
                       const float* __restrict__ resid,
                       bf16* __restrict__ Ch, bf16* __restrict__ Cl) {
    __shared__ float As[16][65];
    __shared__ float Bs[16][68];
    int m0 = blockIdx.y * 64, n0 = blockIdx.x * 64;
    int tid = threadIdx.x;
    int tx = tid & 15, ty = tid >> 4;
    float acc[4][4] = {};

    for (int k0 = 0; k0 < K; k0 += 16) {
        for (int idx = tid; idx < 64 * 16; idx += 256) {
            int i = idx >> 4, kk = idx & 15;
            int m = m0 + i;
            As[kk][i] = (m < M) ? A[(size_t)m * K + k0 + kk] : 0.f;
        }
        for (int idx = tid; idx < 64 * 16; idx += 256) {
            int j = idx >> 4, kk = idx & 15;
            Bs[kk][j] = Bw[(size_t)(n0 + j) * K + k0 + kk];
        }
        __syncthreads();
        #pragma unroll
        for (int kk = 0; kk < 16; kk++) {
            float a[4], bv[4];
            #pragma unroll
            for (int i = 0; i < 4; i++) a[i] = As[kk][ty * 4 + i];
            #pragma unroll
            for (int j = 0; j < 4; j++) bv[j] = Bs[kk][tx * 4 + j];
            #pragma unroll
            for (int i = 0; i < 4; i++)
                #pragma unroll
                for (int j = 0; j < 4; j++) acc[i][j] += a[i] * bv[j];
        }
        __syncthreads();
    }

    #pragma unroll
    for (int i = 0; i < 4; i++) {
        int m = m0 + ty * 4 + i;
        if (m >= M) continue;
        #pragma unroll
        for (int j = 0; j < 4; j++) {
            int n = n0 + tx * 4 + j;
            float v = acc[i][j];
            if (MODE == 1) v += bias[n];
            if (MODE == 2) {
                float s = bng[n] * rsqrtf(1.f + EPS);
                v = resid[(size_t)m * N + n] + fmaxf(v * s + bnb[n], 0.f);
                bf16 hi, lo; split_bf16(v, hi, lo);
                Ch[(size_t)m * N + n] = hi;
                Cl[(size_t)m * N + n] = lo;
            } else {
                C[(size_t)m * N + n] = v;
            }
        }
    }
}

// ---------------- fuse ----------------
__global__ void k_fuse(const float* __restrict__ fuse_w, const float* __restrict__ fuse_b) {
    int bk = blockIdx.x;
    int c = threadIdx.x;
    int b = bk / KK, k = bk % KK;
    float acc = fuse_b[0];
    #pragma unroll 8
    for (int p = 0; p < PP; p++)
        acc += fuse_w[p] * g_Fl2[(((size_t)b * PP + p) * KK + k) * CC + c];
    g_Fg[(size_t)bk * CC + c] = acc;
}

// ---------------- attention ----------------
__global__ void k_attn() {
    int bp = blockIdx.x;
    int b = bp >> 6, p = bp & 63;
    int ph = p >> 3, pw = p & 7;
    int tid = threadIdx.x;
    __shared__ float ks[KK][DD];
    __shared__ float vs[KK][DD];
    for (int idx = tid; idx < KK * DD; idx += 256)
        ((float*)ks)[idx] = g_key[(size_t)bp * KK * DD + idx];
    for (int idx = tid; idx < KK * DD; idx += 256)
        ((float*)vs)[idx] = g_value[(size_t)b * KK * DD + idx];
    __syncthreads();

    int warp = tid >> 5, lane = tid & 31;
    for (int n = warp; n < NN; n += 8) {
        int h = ph * 8 + (n >> 3), w = pw * 8 + (n & 7);
        const float* qrow = &g_query[((size_t)b * HW + h * WW + w) * DD];
        float qr[8];
        #pragma unroll
        for (int i = 0; i < 8; i++) qr[i] = qrow[i * 32 + lane];

        float acc[KK];
        #pragma unroll
        for (int k = 0; k < KK; k++) acc[k] = 0.f;
        #pragma unroll
        for (int i = 0; i < 8; i++) {
            float qd = qr[i];
            #pragma unroll
            for (int k = 0; k < KK; k++) acc[k] += qd * ks[k][i * 32 + lane];
        }
        #pragma unroll
        for (int k = 0; k < KK; k++) {
            #pragma unroll
            for (int off = 16; off > 0; off >>= 1)
                acc[k] += __shfl_xor_sync(0xFFFFFFFFu, acc[k], off);
        }
        float mx = -1e30f;
        #pragma unroll
        for (int k = 0; k < KK; k++) mx = fmaxf(mx, acc[k]);
        float sum = 0.f;
        #pragma unroll
        for (int k = 0; k < KK; k++) { acc[k] = __expf(acc[k] - mx); sum += acc[k]; }
        float inv = 1.f / sum;
        #pragma unroll
        for (int k = 0; k < KK; k++) acc[k] *= inv;

        float* orow = &g_Fs[((size_t)b * HW + h * WW + w) * DD];
        #pragma unroll
        for (int i = 0; i < 8; i++) {
            int d = i * 32 + lane;
            float o = 0.f;
            #pragma unroll
            for (int k = 0; k < KK; k++) o += acc[k] * vs[k][d];
            orow[d] = o;
        }
    }
}

// ---------------- tensor-core 3x3 conv, NHWC, pad=1, split-bf16, BN+ReLU ----------------
// block: 4 output rows (M=256 px) x 128 outch; 512 threads = 16 warps (8 x 2).
// smem: Wh[3][16][128](12288B) | Wl(12288B) | Ah[4][66][16](8448B) | Al(8448B) = 41472B
__global__ __launch_bounds__(512, 1)
void k_conv_mma(const bf16* __restrict__ in_hi, const bf16* __restrict__ in_lo, int Cin,
                const bf16* __restrict__ w_hi, const bf16* __restrict__ w_lo, int OutC,
                const float* __restrict__ bng, const float* __restrict__ bnb,
                float* __restrict__ out_f,
                bf16* __restrict__ out_hi, bf16* __restrict__ out_lo,
                int out_stride) {
    extern __shared__ char smem[];
    bf16* Wh = (bf16*)smem;
    bf16* Wl = (bf16*)(smem + 12288);
    bf16* Ah = (bf16*)(smem + 24576);
    bf16* Al = (bf16*)(smem + 33024);

    int h0 = blockIdx.x * 4, b = blockIdx.y, n0 = blockIdx.z * 128;
    int tid = threadIdx.x;
    int lane = tid & 31, warp = tid >> 5;
    int warpM = warp >> 1, warpN = warp & 1;

    wmma::fragment<wmma::accumulator, 16, 16, 16, float> acc[2][4];
    #pragma unroll
    for (int mt = 0; mt < 2; mt++)
        #pragma unroll
        for (int nj = 0; nj < 4; nj++) wmma::fill_fragment(acc[mt][nj], 0.f);

    for (int ky = 0; ky < 3; ky++) {
        const bf16* wbh = w_hi + (size_t)(ky * 3) * Cin * OutC;
        const bf16* wbl = w_lo + (size_t)(ky * 3) * Cin * OutC;
        for (int c0 = 0; c0 < Cin; c0 += 16) {
            // A tiles: 4 rows x 66 px x 16 ch, hi+lo, uint4 loads
            for (int u = tid; u < 528; u += 512) {
                int flat = u * 8;
                int r = flat / 1056, rem = flat % 1056;
                int wi = rem >> 4, c8 = rem & 15;
                int gh = h0 + r + ky - 1, gw = wi - 1;
                uint4 vh = make_uint4(0, 0, 0, 0), vl = make_uint4(0, 0, 0, 0);
                if (gh >= 0 && gh < HH && gw >= 0 && gw < WW) {
                    size_t g = ((size_t)(b * HH + gh) * WW + gw) * Cin + c0 + c8;
                    vh = *(const uint4*)(in_hi + g);
                    vl = *(const uint4*)(in_lo + g);
                }
                *(uint4*)(Ah + flat) = vh;
                *(uint4*)(Al + flat) = vl;
            }
            // W tiles: 3 kx x 16 ch x 128 outch, hi+lo, uint4 loads
            for (int u = tid; u < 768; u += 512) {
                int flat = u * 8;
                int kx = flat >> 11, rem = flat & 2047;
                int ck = rem >> 7, o = rem & 127;
                size_t g = ((size_t)kx * Cin + c0 + ck) * OutC + n0 + o;
                *(uint4*)(Wh + flat) = *(const uint4*)(wbh + g);
                *(uint4*)(Wl + flat) = *(const uint4*)(wbl + g);
            }
            __syncthreads();

            #pragma unroll
            for (int mt = 0; mt < 2; mt++) {
                int t = warpM * 2 + mt;
                int abase = (t >> 2) * 66 + (t & 3) * 16;
                #pragma unroll
                for (int kx = 0; kx < 3; kx++) {
                    wmma::fragment<wmma::matrix_a, 16, 16, 16, bf16, wmma::row_major> ah, al;
                    wmma::load_matrix_sync(ah, Ah + (abase + kx) * 16, 16);
                    wmma::load_matrix_sync(al, Al + (abase + kx) * 16, 16);
                    #pragma unroll
                    for (int nj = 0; nj < 4; nj++) {
                        wmma::fragment<wmma::matrix_b, 16, 16, 16, bf16, wmma::row_major> bh, bl;
                        int boff = kx * 2048 + warpN * 64 + nj * 16;
                        wmma::load_matrix_sync(bh, Wh + boff, 128);
                        wmma::load_matrix_sync(bl, Wl + boff, 128);
                        wmma::mma_sync(acc[mt][nj], ah, bh, acc[mt][nj]);
                        wmma::mma_sync(acc[mt][nj], ah, bl, acc[mt][nj]);
                        wmma::mma_sync(acc[mt][nj], al, bh, acc[mt][nj]);
                    }
                }
            }
            __syncthreads();
        }
    }

    // per-warp staged epilogue (reuse smem; all block syncs already passed)
    float* buf = (float*)smem + warp * 320;   // 16 x 20 floats
    #pragma unroll
    for (int mt = 0; mt < 2; mt++) {
        int t = warpM * 2 + mt;
        int row_l = t >> 2, px0 = (t & 3) * 16;
        size_t rowbase = (size_t)(b * HH + h0 + row_l) * WW;
        #pragma unroll
        for (int nj = 0; nj < 4; nj++) {
            wmma::store_matrix_sync(buf, acc[mt][nj], 20, wmma::mem_row_major);
            __syncwarp();
            #pragma unroll
            for (int l = 0; l < 8; l++) {
                int e = l * 32 + lane;
                int r = e >> 4, c = e & 15;
                int gn = n0 + warpN * 64 + nj * 16 + c;
                float v = buf[r * 20 + c];
                float s = bng[gn] * rsqrtf(1.f + EPS);
                v = fmaxf(v * s + bnb[gn], 0.f);
                size_t o = (rowbase + px0 + r) * out_stride + gn;
                if (out_f) {
                    out_f[o] = v;
                } else {
                    bf16 hi, lo; split_bf16(v, hi, lo);
                    out_hi[o] = hi; out_lo[o] = lo;
                }
            }
            __syncwarp();
        }
    }
}

// ---------------- final 1x1 classifier -> NCHW ----------------
__global__ void k_classifier(const float* __restrict__ drop_w, float* __restrict__ out) {
    __shared__ float Xs[32][65];
    __shared__ float Ws[KK][33];
    int tid = threadIdx.x;
    int row0 = blockIdx.x * 64;
    int b = row0 >> 12;
    int hw0 = row0 & 4095;
    float acc[5] = {0.f, 0.f, 0.f, 0.f, 0.f};

    for (int c0 = 0; c0 < CC; c0 += 32) {
        for (int idx = tid; idx < 64 * 32; idx += 256) {
            int r = idx >> 5, cc = idx & 31;
            Xs[cc][r] = g_x3[(size_t)(row0 + r) * CC + c0 + cc];
        }
        for (int idx = tid; idx < KK * 32; idx += 256) {
            int k = idx >> 5, cc = idx & 31;
            Ws[k][cc] = drop_w[(size_t)k * CC + c0 + cc];
        }
        __syncthreads();
        #pragma unroll
        for (int sIdx = 0; sIdx < 5; sIdx++) {
            int o = tid + sIdx * 256;
            if (o < KK * 64) {
                int k = o >> 6, r = o & 63;
                float a = acc[sIdx];
                #pragma unroll 8
                for (int cc = 0; cc < 32; cc++) a += Ws[k][cc] * Xs[cc][r];
                acc[sIdx] = a;
            }
        }
        __syncthreads();
    }
    #pragma unroll
    for (int sIdx = 0; sIdx < 5; sIdx++) {
        int o = tid + sIdx * 256;
        if (o < KK * 64) {
            int k = o >> 6, r = o & 63;
            out[((size_t)b * KK + k) * HW + hw0 + r] = acc[sIdx];
        }
    }
}

// ---------------- launch ----------------
extern "C" void kernel_launch(void* const* d_in, const int* in_sizes, int n_in,
                              void* d_out, int out_size) {
    const float* M_1   = (const float*)d_in[0];
    const float* F     = (const float*)d_in[1];
    const float* I     = (const float*)d_in[2];
    const float* R     = (const float*)d_in[3];
    const float* lg_w1 = (const float*)d_in[4];
    const float* lg_w2 = (const float*)d_in[5];
    const float* fuse_w= (const float*)d_in[6];
    const float* fuse_b= (const float*)d_in[7];
    const float* q_w   = (const float*)d_in[8];
    const float* q_b   = (const float*)d_in[9];
    const float* k_w   = (const float*)d_in[10];
    const float* k_b   = (const float*)d_in[11];
    const float* v_w   = (const float*)d_in[12];
    const float* v_b   = (const float*)d_in[13];
    const float* c1_w  = (const float*)d_in[14];
    const float* bn1_g = (const float*)d_in[15];
    const float* bn1_b = (const float*)d_in[16];
    const float* c2_w  = (const float*)d_in[17];
    const float* bn2_g = (const float*)d_in[18];
    const float* bn2_b = (const float*)d_in[19];
    const float* c3_w  = (const float*)d_in[20];
    const float* bn3_g = (const float*)d_in[21];
    const float* bn3_b = (const float*)d_in[22];
    const float* drop_w= (const float*)d_in[23];
    float* out = (float*)d_out;

    float *p_Fnhwc, *p_Fl, *p_h, *p_Fl2, *p_Fg, *p_q, *p_k, *p_v, *p_Fs, *p_x3;
    bf16 *p_cath, *p_catl, *p_Fo1h, *p_Fo1l, *p_w2h, *p_w2l, *p_w3h, *p_w3l;
    cudaGetSymbolAddress((void**)&p_Fnhwc, g_Fnhwc);
    cudaGetSymbolAddress((void**)&p_Fl,    g_Fl);
    cudaGetSymbolAddress((void**)&p_h,     g_h);
    cudaGetSymbolAddress((void**)&p_Fl2,   g_Fl2);
    cudaGetSymbolAddress((void**)&p_Fg,    g_Fg);
    cudaGetSymbolAddress((void**)&p_q,     g_query);
    cudaGetSymbolAddress((void**)&p_k,     g_key);
    cudaGetSymbolAddress((void**)&p_v,     g_value);
    cudaGetSymbolAddress((void**)&p_Fs,    g_Fs);
    cudaGetSymbolAddress((void**)&p_x3,    g_x3);
    cudaGetSymbolAddress((void**)&p_cath,  g_cath);
    cudaGetSymbolAddress((void**)&p_catl,  g_catl);
    cudaGetSymbolAddress((void**)&p_Fo1h,  g_Fo1h);
    cudaGetSymbolAddress((void**)&p_Fo1l,  g_Fo1l);
    cudaGetSymbolAddress((void**)&p_w2h,   g_w2h);
    cudaGetSymbolAddress((void**)&p_w2l,   g_w2l);
    cudaGetSymbolAddress((void**)&p_w3h,   g_w3h);
    cudaGetSymbolAddress((void**)&p_w3l,   g_w3l);

    dim3 blk32(32, 8);
    const int CONV_SMEM = 41472;

    k_wsplit<<<(512 * 512 * 9 + 255) / 256, 256>>>(c2_w, p_w2h, p_w2l, 512, 512);
    k_wsplit<<<(512 * 2560 * 9 + 255) / 256, 256>>>(c3_w, p_w3h, p_w3l, 512, 2560);

    k_transpose<<<dim3(HW / 32, CC / 32, BATCH), blk32>>>(F, p_Fnhwc, CC, CC, 0);
    k_transpose_pair<<<dim3(HW / 32, 2048 / 32, BATCH), blk32>>>(M_1, p_cath, p_catl, 2048, CIN3, CC);
    k_patch_fl<<<BATCH * PP, 256>>>(I, R);
    k_lg1<<<dim3(CC / 64, BATCH * KK), 256>>>(lg_w1);
    k_gemm<0><<<dim3(CC / 64, (BATCH * PP * KK) / 64), 256>>>(
        p_h, lg_w2, p_Fl2, BATCH * PP * KK, CC, CC, nullptr, nullptr, nullptr, nullptr, nullptr, nullptr);
    k_fuse<<<BATCH * KK, CC>>>(fuse_w, fuse_b);
    k_gemm<1><<<dim3(DD / 64, (BATCH * HW) / 64), 256>>>(
        p_Fnhwc, q_w, p_q, BATCH * HW, DD, CC, q_b, nullptr, nullptr, nullptr, nullptr, nullptr);
    k_gemm<1><<<dim3(DD / 64, (BATCH * PP * KK) / 64), 256>>>(
        p_Fl2, k_w, p_k, BATCH * PP * KK, DD, CC, k_b, nullptr, nullptr, nullptr, nullptr, nullptr);
    k_gemm<1><<<dim3(DD / 64, (BATCH * KK + 63) / 64), 256>>>(
        p_Fg, v_w, p_v, BATCH * KK, DD, CC, v_b, nullptr, nullptr, nullptr, nullptr, nullptr);
    k_attn<<<BATCH * PP, 256>>>();
    k_gemm<2><<<dim3(CC / 64, (BATCH * HW) / 64), 256>>>(
        p_Fs, c1_w, nullptr, BATCH * HW, CC, DD, nullptr, bn1_g, bn1_b, p_Fnhwc, p_Fo1h, p_Fo1l);

    // conv2: Fo1(512) -> cat[:,0:512) bf16 pair
    k_conv_mma<<<dim3(HH / 4, BATCH, 4), 512, CONV_SMEM>>>(
        p_Fo1h, p_Fo1l, CC, p_w2h, p_w2l, 512, bn2_g, bn2_b,
        nullptr, p_cath, p_catl, CIN3);
    // conv3: cat(2560) -> x3 fp32
    k_conv_mma<<<dim3(HH / 4, BATCH, 4), 512, CONV_SMEM>>>(
        p_cath, p_catl, CIN3, p_w3h, p_w3l, 512, bn3_g, bn3_b,
        p_x3, nullptr, nullptr, CC);

    k_classifier<<<(BATCH * HW) / 64, 256>>>(drop_w, out);
}

// round 5
// speedup vs baseline: 5.1601x; 2.1697x over previous
#include <cuda_runtime.h>
#include <cuda_bf16.h>
#include <mma.h>
#include <math.h>
#include <stdint.h>

using namespace nvcuda;
typedef __nv_bfloat16 bf16;

#define EPS 1e-5f

#define BATCH 4
#define HH 64
#define WW 64
#define HW 4096
#define CC 512
#define KK 19
#define PP 64
#define NN 64
#define DD 256
#define CIN3 2560

// ---------------- scratch ----------------
__device__ float g_Fnhwc[BATCH * HW * CC];
__device__ float g_Fl[BATCH * PP * KK * CC];
__device__ float g_h[BATCH * PP * KK * CC];
__device__ float g_Fl2[BATCH * PP * KK * CC];
__device__ float g_Fg[BATCH * KK * CC];
__device__ float g_query[BATCH * HW * DD];
__device__ float g_key[BATCH * PP * KK * DD];
__device__ float g_value[BATCH * KK * DD];
__device__ float g_Fs[BATCH * HW * DD];
__device__ float g_x3[BATCH * HW * CC];

__device__ bf16 g_cath[(size_t)BATCH * HW * CIN3];
__device__ bf16 g_catl[(size_t)BATCH * HW * CIN3];
__device__ bf16 g_Fo1h[BATCH * HW * CC];
__device__ bf16 g_Fo1l[BATCH * HW * CC];
__device__ bf16 g_w2h[512 * 512 * 9];
__device__ bf16 g_w2l[512 * 512 * 9];
__device__ bf16 g_w3h[512 * 2560 * 9];
__device__ bf16 g_w3l[512 * 2560 * 9];

__device__ __forceinline__ void split_bf16(float v, bf16& hi, bf16& lo) {
    hi = __float2bfloat16(v);
    lo = __float2bfloat16(v - __bfloat162float(hi));
}

// cp.async helpers
__device__ __forceinline__ void cpa16(void* sdst, const void* gsrc, bool pred) {
    unsigned int s = (unsigned int)__cvta_generic_to_shared(sdst);
    int sz = pred ? 16 : 0;
    asm volatile("cp.async.cg.shared.global [%0], [%1], 16, %2;" :: "r"(s), "l"(gsrc), "r"(sz));
}
__device__ __forceinline__ void cpa_commit() {
    asm volatile("cp.async.commit_group;");
}
template <int N>
__device__ __forceinline__ void cpa_wait() {
    asm volatile("cp.async.wait_group %0;" :: "n"(N));
}

// ---------------- transpose NCHW -> NHWC (fp32) ----------------
__global__ void k_transpose(const float* __restrict__ in, float* __restrict__ out,
                            int C, int out_stride, int col_off) {
    __shared__ float tile[32][33];
    int b = blockIdx.z;
    int hw0 = blockIdx.x * 32, c0 = blockIdx.y * 32;
    int tx = threadIdx.x, ty = threadIdx.y;
    for (int i = ty; i < 32; i += 8)
        tile[i][tx] = in[((size_t)b * C + c0 + i) * HW + hw0 + tx];
    __syncthreads();
    for (int i = ty; i < 32; i += 8)
        out[((size_t)b * HW + hw0 + i) * out_stride + col_off + c0 + tx] = tile[tx][i];
}

// ---------------- transpose NCHW -> NHWC (bf16 hi/lo) ----------------
__global__ void k_transpose_pair(const float* __restrict__ in, bf16* __restrict__ oh,
                                 bf16* __restrict__ ol, int C, int out_stride, int col_off) {
    __shared__ float tile[32][33];
    int b = blockIdx.z;
    int hw0 = blockIdx.x * 32, c0 = blockIdx.y * 32;
    int tx = threadIdx.x, ty = threadIdx.y;
    for (int i = ty; i < 32; i += 8)
        tile[i][tx] = in[((size_t)b * C + c0 + i) * HW + hw0 + tx];
    __syncthreads();
    for (int i = ty; i < 32; i += 8) {
        float v = tile[tx][i];
        bf16 hi, lo; split_bf16(v, hi, lo);
        size_t o = ((size_t)b * HW + hw0 + i) * out_stride + col_off + c0 + tx;
        oh[o] = hi; ol[o] = lo;
    }
}

// ---------------- weight split, dst-ordered (coalesced writes) ----------------
// dst layout [(ky*3+kx)][Cin][OutC], src OIHW
__global__ void k_wsplit(const float* __restrict__ w, bf16* __restrict__ oh,
                         bf16* __restrict__ ol, int OutC, int Cin) {
    size_t d = (size_t)blockIdx.x * 256 + threadIdx.x;
    size_t total = (size_t)OutC * Cin * 9;
    if (d >= total) return;
    int o = d % OutC;
    size_t t2 = d / OutC;
    int i = t2 % Cin;
    int kq = t2 / Cin;
    float v = w[((size_t)o * Cin + i) * 9 + kq];
    bf16 hi, lo; split_bf16(v, hi, lo);
    oh[d] = hi; ol[d] = lo;
}

// ---------------- patch softmax + F_l ----------------
__global__ void k_patch_fl(const float* __restrict__ I, const float* __restrict__ R) {
    int bp = blockIdx.x;
    int b = bp >> 6, p = bp & 63;
    int ph = p >> 3, pw = p & 7;
    int tid = threadIdx.x;

    __shared__ float lg[KK][NN];
    __shared__ float pix[NN][20];
    __shared__ float bc[KK];
    __shared__ float Fp[NN][65];

    for (int idx = tid; idx < KK * NN; idx += 256) {
        int k = idx / NN, n = idx % NN;
        int h = ph * 8 + (n >> 3), w = pw * 8 + (n & 7);
        lg[k][n] = I[(((size_t)b * KK + k) * HH + h) * WW + w];
    }
    if (tid < KK) bc[tid] = R[((size_t)b * KK + tid) * PP + p];
    __syncthreads();

    if (tid < KK) {
        float mx = -1e30f;
        for (int n = 0; n < NN; n++) mx = fmaxf(mx, lg[tid][n]);
        float s = 0.f;
        for (int n = 0; n < NN; n++) { float e = __expf(lg[tid][n] - mx); pix[n][tid] = e; s += e; }
        float inv = 1.f / s;
        for (int n = 0; n < NN; n++) pix[n][tid] *= inv;
    }
    __syncthreads();

    for (int c0 = 0; c0 < CC; c0 += 64) {
        for (int idx = tid; idx < NN * 64; idx += 256) {
            int n = idx >> 6, cc = idx & 63;
            int h = ph * 8 + (n >> 3), w = pw * 8 + (n & 7);
            Fp[n][cc] = g_Fnhwc[((size_t)b * HW + h * WW + w) * CC + c0 + cc];
        }
        __syncthreads();
        for (int o = tid; o < KK * 64; o += 256) {
            int k = o >> 6, cc = o & 63;
            float acc = 0.f;
            #pragma unroll 8
            for (int n = 0; n < NN; n++) acc += pix[n][k] * Fp[n][cc];
            g_Fl[((size_t)bp * KK + k) * CC + c0 + cc] = acc * bc[k];
        }
        __syncthreads();
    }
}

// ---------------- h = relu(lg_w1 @p F_l + F_l) ----------------
__global__ void k_lg1(const float* __restrict__ lg_w1) {
    int c0 = blockIdx.x * 64;
    int bk = blockIdx.y;
    int b = bk / KK, k = bk % KK;
    int tid = threadIdx.x;
    __shared__ float w1[64][64];
    __shared__ float Fl[64][65];
    for (int idx = tid; idx < 4096; idx += 256) w1[idx >> 6][idx & 63] = lg_w1[idx];
    for (int idx = tid; idx < 4096; idx += 256) {
        int p = idx >> 6, cc = idx & 63;
        Fl[p][cc] = g_Fl[(((size_t)b * PP + p) * KK + k) * CC + c0 + cc];
    }
    __syncthreads();
    for (int o = tid; o < 4096; o += 256) {
        int q = o >> 6, cc = o & 63;
        float acc = Fl[q][cc];
        #pragma unroll 8
        for (int p = 0; p < 64; p++) acc += w1[q][p] * Fl[p][cc];
        g_h[(((size_t)b * PP + q) * KK + k) * CC + c0 + cc] = fmaxf(acc, 0.f);
    }
}

// ---------------- generic fp32 GEMM ----------------
template <int MODE>
__global__ void k_gemm(const float* __restrict__ A, const float* __restrict__ Bw,
                       float* __restrict__ C, int M, int N, int K,
                       const float* __restrict__ bias,
                       const float* __restrict__ bng, const float* __restrict__ bnb,
                       const float* __restrict__ resid,
                       bf16* __restrict__ Ch, bf16* __restrict__ Cl) {
    __shared__ float As[16][68];
    __shared__ float Bs[16][68];
    int m0 = blockIdx.y * 64, n0 = blockIdx.x * 64;
    int tid = threadIdx.x;
    int tx = tid & 15, ty = tid >> 4;
    float acc[4][4] = {};

    for (int k0 = 0; k0 < K; k0 += 16) {
        for (int idx = tid; idx < 64 * 16; idx += 256) {
            int i = idx >> 4, kk = idx & 15;
            int m = m0 + i;
            As[kk][i] = (m < M) ? A[(size_t)m * K + k0 + kk] : 0.f;
        }
        for (int idx = tid; idx < 64 * 16; idx += 256) {
            int j = idx >> 4, kk = idx & 15;
            Bs[kk][j] = Bw[(size_t)(n0 + j) * K + k0 + kk];
        }
        __syncthreads();
        #pragma unroll
        for (int kk = 0; kk < 16; kk++) {
            float a[4], bv[4];
            #pragma unroll
            for (int i = 0; i < 4; i++) a[i] = As[kk][ty * 4 + i];
            #pragma unroll
            for (int j = 0; j < 4; j++) bv[j] = Bs[kk][tx * 4 + j];
            #pragma unroll
            for (int i = 0; i < 4; i++)
                #pragma unroll
                for (int j = 0; j < 4; j++) acc[i][j] += a[i] * bv[j];
        }
        __syncthreads();
    }

    #pragma unroll
    for (int i = 0; i < 4; i++) {
        int m = m0 + ty * 4 + i;
        if (m >= M) continue;
        #pragma unroll
        for (int j = 0; j < 4; j++) {
            int n = n0 + tx * 4 + j;
            float v = acc[i][j];
            if (MODE == 1) v += bias[n];
            if (MODE == 2) {
                float s = bng[n] * rsqrtf(1.f + EPS);
                v = resid[(size_t)m * N + n] + fmaxf(v * s + bnb[n], 0.f);
                bf16 hi, lo; split_bf16(v, hi, lo);
                Ch[(size_t)m * N + n] = hi;
                Cl[(size_t)m * N + n] = lo;
            } else {
                C[(size_t)m * N + n] = v;
            }
        }
    }
}

// ---------------- fuse ----------------
__global__ void k_fuse(const float* __restrict__ fuse_w, const float* __restrict__ fuse_b) {
    int bk = blockIdx.x;
    int c = threadIdx.x;
    int b = bk / KK, k = bk % KK;
    float acc = fuse_b[0];
    #pragma unroll 8
    for (int p = 0; p < PP; p++)
        acc += fuse_w[p] * g_Fl2[(((size_t)b * PP + p) * KK + k) * CC + c];
    g_Fg[(size_t)bk * CC + c] = acc;
}

// ---------------- attention ----------------
__global__ void k_attn() {
    int bp = blockIdx.x;
    int b = bp >> 6, p = bp & 63;
    int ph = p >> 3, pw = p & 7;
    int tid = threadIdx.x;
    __shared__ float ks[KK][DD];
    __shared__ float vs[KK][DD];
    for (int idx = tid; idx < KK * DD; idx += 256)
        ((float*)ks)[idx] = g_key[(size_t)bp * KK * DD + idx];
    for (int idx = tid; idx < KK * DD; idx += 256)
        ((float*)vs)[idx] = g_value[(size_t)b * KK * DD + idx];
    __syncthreads();

    int warp = tid >> 5, lane = tid & 31;
    for (int n = warp; n < NN; n += 8) {
        int h = ph * 8 + (n >> 3), w = pw * 8 + (n & 7);
        const float* qrow = &g_query[((size_t)b * HW + h * WW + w) * DD];
        float qr[8];
        #pragma unroll
        for (int i = 0; i < 8; i++) qr[i] = qrow[i * 32 + lane];

        float acc[KK];
        #pragma unroll
        for (int k = 0; k < KK; k++) acc[k] = 0.f;
        #pragma unroll
        for (int i = 0; i < 8; i++) {
            float qd = qr[i];
            #pragma unroll
            for (int k = 0; k < KK; k++) acc[k] += qd * ks[k][i * 32 + lane];
        }
        #pragma unroll
        for (int k = 0; k < KK; k++) {
            #pragma unroll
            for (int off = 16; off > 0; off >>= 1)
                acc[k] += __shfl_xor_sync(0xFFFFFFFFu, acc[k], off);
        }
        float mx = -1e30f;
        #pragma unroll
        for (int k = 0; k < KK; k++) mx = fmaxf(mx, acc[k]);
        float sum = 0.f;
        #pragma unroll
        for (int k = 0; k < KK; k++) { acc[k] = __expf(acc[k] - mx); sum += acc[k]; }
        float inv = 1.f / sum;
        #pragma unroll
        for (int k = 0; k < KK; k++) acc[k] *= inv;

        float* orow = &g_Fs[((size_t)b * HW + h * WW + w) * DD];
        #pragma unroll
        for (int i = 0; i < 8; i++) {
            int d = i * 32 + lane;
            float o = 0.f;
            #pragma unroll
            for (int k = 0; k < KK; k++) o += acc[k] * vs[k][d];
            orow[d] = o;
        }
    }
}

// ---------------- tensor-core 3x3 conv: cp.async 2-stage, conflict-padded W ----------------
// block: 4 output rows (M=256 px) x 128 outch; 512 threads = 16 warps (8 warpM x 2 warpN)
// Stage layout (bytes): Ah[4*66*16]=8448 | Al=8448 | Wh[3*16*136]=13056 | Wl=13056 = 43008
#define STAGE_B 43008
__global__ __launch_bounds__(512, 1)
void k_conv_mma(const bf16* __restrict__ in_hi, const bf16* __restrict__ in_lo, int Cin,
                const bf16* __restrict__ w_hi, const bf16* __restrict__ w_lo, int OutC,
                const float* __restrict__ bng, const float* __restrict__ bnb,
                float* __restrict__ out_f,
                bf16* __restrict__ out_hi, bf16* __restrict__ out_lo,
                int out_stride) {
    extern __shared__ char smem[];
    int h0 = blockIdx.x * 4, b = blockIdx.y, n0 = blockIdx.z * 128;
    int tid = threadIdx.x;
    int lane = tid & 31, warp = tid >> 5;
    int warpM = warp >> 1, warpN = warp & 1;
    int csteps = Cin >> 4;
    int iters = 3 * csteps;

    wmma::fragment<wmma::accumulator, 16, 16, 16, float> acc[2][4];
    #pragma unroll
    for (int mt = 0; mt < 2; mt++)
        #pragma unroll
        for (int nj = 0; nj < 4; nj++) wmma::fill_fragment(acc[mt][nj], 0.f);

    // ---- stage issue ----
    auto issue = [&](int it) {
        int ky = it / csteps;
        int c0 = (it - ky * csteps) << 4;
        char* base = smem + (it & 1) * STAGE_B;
        bf16* Ah = (bf16*)base;
        bf16* Al = (bf16*)(base + 8448);
        bf16* Wh = (bf16*)(base + 16896);
        bf16* Wl = (bf16*)(base + 29952);
        // A: 4 rows x 66 px x 16 ch (hi 528 uint4 + lo 528)
        for (int u = tid; u < 1056; u += 512) {
            int v = (u < 528) ? u : u - 528;
            int flat = v * 8;
            int r = flat / 1056, rem = flat % 1056;
            int wi = rem >> 4, c8 = rem & 15;
            int gh = h0 + r + ky - 1, gw = wi - 1;
            bool pred = (gh >= 0 && gh < HH && gw >= 0 && gw < WW);
            const bf16* src = (u < 528) ? in_hi : in_lo;
            const bf16* g = pred ? (src + ((size_t)(b * HH + gh) * WW + gw) * Cin + c0 + c8) : src;
            bf16* dst = ((u < 528) ? Ah : Al) + (r * 66 + wi) * 16 + c8;
            cpa16(dst, g, pred);
        }
        // W: 3 kx x 16 ch x 128 outch (hi 768 uint4 + lo 768), padded rows (136)
        for (int u = tid; u < 1536; u += 512) {
            int v = (u < 768) ? u : u - 768;
            int flat = v * 8;
            int kx = flat >> 11, rem = flat & 2047;
            int ck = rem >> 7, o8 = rem & 127;
            const bf16* src = (u < 768) ? w_hi : w_lo;
            const bf16* g = src + ((size_t)(ky * 3 + kx) * Cin + c0 + ck) * OutC + n0 + o8;
            bf16* dst = ((u < 768) ? Wh : Wl) + kx * 2176 + ck * 136 + o8;
            cpa16(dst, g, true);
        }
        cpa_commit();
    };

    issue(0);

    for (int it = 0; it < iters; it++) {
        cpa_wait<0>();
        __syncthreads();
        if (it + 1 < iters) issue(it + 1);

        char* base = smem + (it & 1) * STAGE_B;
        bf16* Ah = (bf16*)base;
        bf16* Al = (bf16*)(base + 8448);
        bf16* Wh = (bf16*)(base + 16896);
        bf16* Wl = (bf16*)(base + 29952);

        #pragma unroll
        for (int mt = 0; mt < 2; mt++) {
            int t = warpM * 2 + mt;
            int pbase = (t >> 2) * 66 + (t & 3) * 16;
            #pragma unroll
            for (int kx = 0; kx < 3; kx++) {
                wmma::fragment<wmma::matrix_a, 16, 16, 16, bf16, wmma::row_major> ah, al;
                wmma::load_matrix_sync(ah, Ah + (pbase + kx) * 16, 16);
                wmma::load_matrix_sync(al, Al + (pbase + kx) * 16, 16);
                #pragma unroll
                for (int nj = 0; nj < 4; nj++) {
                    wmma::fragment<wmma::matrix_b, 16, 16, 16, bf16, wmma::row_major> bh, bl;
                    int boff = kx * 2176 + warpN * 64 + nj * 16;
                    wmma::load_matrix_sync(bh, Wh + boff, 136);
                    wmma::load_matrix_sync(bl, Wl + boff, 136);
                    wmma::mma_sync(acc[mt][nj], ah, bh, acc[mt][nj]);
                    wmma::mma_sync(acc[mt][nj], ah, bl, acc[mt][nj]);
                    wmma::mma_sync(acc[mt][nj], al, bh, acc[mt][nj]);
                }
            }
        }
        __syncthreads();
    }

    // epilogue: per-warp smem staging (reuse smem)
    float* buf = (float*)smem + warp * 320;
    #pragma unroll
    for (int mt = 0; mt < 2; mt++) {
        int t = warpM * 2 + mt;
        int row_l = t >> 2, px0 = (t & 3) * 16;
        size_t rowbase = (size_t)(b * HH + h0 + row_l) * WW;
        #pragma unroll
        for (int nj = 0; nj < 4; nj++) {
            wmma::store_matrix_sync(buf, acc[mt][nj], 20, wmma::mem_row_major);
            __syncwarp();
            #pragma unroll
            for (int l = 0; l < 8; l++) {
                int e = l * 32 + lane;
                int r = e >> 4, c = e & 15;
                int gn = n0 + warpN * 64 + nj * 16 + c;
                float v = buf[r * 20 + c];
                float s = bng[gn] * rsqrtf(1.f + EPS);
                v = fmaxf(v * s + bnb[gn], 0.f);
                size_t o = (rowbase + px0 + r) * out_stride + gn;
                if (out_f) {
                    out_f[o] = v;
                } else {
                    bf16 hi, lo; split_bf16(v, hi, lo);
                    out_hi[o] = hi; out_lo[o] = lo;
                }
            }
            __syncwarp();
        }
    }
}

// ---------------- final 1x1 classifier -> NCHW ----------------
__global__ void k_classifier(const float* __restrict__ drop_w, float* __restrict__ out) {
    __shared__ float Xs[32][65];
    __shared__ float Ws[KK][33];
    int tid = threadIdx.x;
    int row0 = blockIdx.x * 64;
    int b = row0 >> 12;
    int hw0 = row0 & 4095;
    float acc[5] = {0.f, 0.f, 0.f, 0.f, 0.f};

    for (int c0 = 0; c0 < CC; c0 += 32) {
        for (int idx = tid; idx < 64 * 32; idx += 256) {
            int r = idx >> 5, cc = idx & 31;
            Xs[cc][r] = g_x3[(size_t)(row0 + r) * CC + c0 + cc];
        }
        for (int idx = tid; idx < KK * 32; idx += 256) {
            int k = idx >> 5, cc = idx & 31;
            Ws[k][cc] = drop_w[(size_t)k * CC + c0 + cc];
        }
        __syncthreads();
        #pragma unroll
        for (int sIdx = 0; sIdx < 5; sIdx++) {
            int o = tid + sIdx * 256;
            if (o < KK * 64) {
                int k = o >> 6, r = o & 63;
                float a = acc[sIdx];
                #pragma unroll 8
                for (int cc = 0; cc < 32; cc++) a += Ws[k][cc] * Xs[cc][r];
                acc[sIdx] = a;
            }
        }
        __syncthreads();
    }
    #pragma unroll
    for (int sIdx = 0; sIdx < 5; sIdx++) {
        int o = tid + sIdx * 256;
        if (o < KK * 64) {
            int k = o >> 6, r = o & 63;
            out[((size_t)b * KK + k) * HW + hw0 + r] = acc[sIdx];
        }
    }
}

// ---------------- launch ----------------
extern "C" void kernel_launch(void* const* d_in, const int* in_sizes, int n_in,
                              void* d_out, int out_size) {
    const float* M_1   = (const float*)d_in[0];
    const float* F     = (const float*)d_in[1];
    const float* I     = (const float*)d_in[2];
    const float* R     = (const float*)d_in[3];
    const float* lg_w1 = (const float*)d_in[4];
    const float* lg_w2 = (const float*)d_in[5];
    const float* fuse_w= (const float*)d_in[6];
    const float* fuse_b= (const float*)d_in[7];
    const float* q_w   = (const float*)d_in[8];
    const float* q_b   = (const float*)d_in[9];
    const float* k_w   = (const float*)d_in[10];
    const float* k_b   = (const float*)d_in[11];
    const float* v_w   = (const float*)d_in[12];
    const float* v_b   = (const float*)d_in[13];
    const float* c1_w  = (const float*)d_in[14];
    const float* bn1_g = (const float*)d_in[15];
    const float* bn1_b = (const float*)d_in[16];
    const float* c2_w  = (const float*)d_in[17];
    const float* bn2_g = (const float*)d_in[18];
    const float* bn2_b = (const float*)d_in[19];
    const float* c3_w  = (const float*)d_in[20];
    const float* bn3_g = (const float*)d_in[21];
    const float* bn3_b = (const float*)d_in[22];
    const float* drop_w= (const float*)d_in[23];
    float* out = (float*)d_out;

    float *p_Fnhwc, *p_Fl, *p_h, *p_Fl2, *p_Fg, *p_q, *p_k, *p_v, *p_Fs, *p_x3;
    bf16 *p_cath, *p_catl, *p_Fo1h, *p_Fo1l, *p_w2h, *p_w2l, *p_w3h, *p_w3l;
    cudaGetSymbolAddress((void**)&p_Fnhwc, g_Fnhwc);
    cudaGetSymbolAddress((void**)&p_Fl,    g_Fl);
    cudaGetSymbolAddress((void**)&p_h,     g_h);
    cudaGetSymbolAddress((void**)&p_Fl2,   g_Fl2);
    cudaGetSymbolAddress((void**)&p_Fg,    g_Fg);
    cudaGetSymbolAddress((void**)&p_q,     g_query);
    cudaGetSymbolAddress((void**)&p_k,     g_key);
    cudaGetSymbolAddress((void**)&p_v,     g_value);
    cudaGetSymbolAddress((void**)&p_Fs,    g_Fs);
    cudaGetSymbolAddress((void**)&p_x3,    g_x3);
    cudaGetSymbolAddress((void**)&p_cath,  g_cath);
    cudaGetSymbolAddress((void**)&p_catl,  g_catl);
    cudaGetSymbolAddress((void**)&p_Fo1h,  g_Fo1h);
    cudaGetSymbolAddress((void**)&p_Fo1l,  g_Fo1l);
    cudaGetSymbolAddress((void**)&p_w2h,   g_w2h);
    cudaGetSymbolAddress((void**)&p_w2l,   g_w2l);
    cudaGetSymbolAddress((void**)&p_w3h,   g_w3h);
    cudaGetSymbolAddress((void**)&p_w3l,   g_w3l);

    dim3 blk32(32, 8);
    const int CONV_SMEM = 2 * STAGE_B;   // 86016 B
    cudaFuncSetAttribute(k_conv_mma, cudaFuncAttributeMaxDynamicSharedMemorySize, CONV_SMEM);

    k_wsplit<<<(512 * 512 * 9 + 255) / 256, 256>>>(c2_w, p_w2h, p_w2l, 512, 512);
    k_wsplit<<<(512 * 2560 * 9 + 255) / 256, 256>>>(c3_w, p_w3h, p_w3l, 512, 2560);

    k_transpose<<<dim3(HW / 32, CC / 32, BATCH), blk32>>>(F, p_Fnhwc, CC, CC, 0);
    k_transpose_pair<<<dim3(HW / 32, 2048 / 32, BATCH), blk32>>>(M_1, p_cath, p_catl, 2048, CIN3, CC);
    k_patch_fl<<<BATCH * PP, 256>>>(I, R);
    k_lg1<<<dim3(CC / 64, BATCH * KK), 256>>>(lg_w1);
    k_gemm<0><<<dim3(CC / 64, (BATCH * PP * KK) / 64), 256>>>(
        p_h, lg_w2, p_Fl2, BATCH * PP * KK, CC, CC, nullptr, nullptr, nullptr, nullptr, nullptr, nullptr);
    k_fuse<<<BATCH * KK, CC>>>(fuse_w, fuse_b);
    k_gemm<1><<<dim3(DD / 64, (BATCH * HW) / 64), 256>>>(
        p_Fnhwc, q_w, p_q, BATCH * HW, DD, CC, q_b, nullptr, nullptr, nullptr, nullptr, nullptr);
    k_gemm<1><<<dim3(DD / 64, (BATCH * PP * KK) / 64), 256>>>(
        p_Fl2, k_w, p_k, BATCH * PP * KK, DD, CC, k_b, nullptr, nullptr, nullptr, nullptr, nullptr);
    k_gemm<1><<<dim3(DD / 64, (BATCH * KK + 63) / 64), 256>>>(
        p_Fg, v_w, p_v, BATCH * KK, DD, CC, v_b, nullptr, nullptr, nullptr, nullptr, nullptr);
    k_attn<<<BATCH * PP, 256>>>();
    k_gemm<2><<<dim3(CC / 64, (BATCH * HW) / 64), 256>>>(
        p_Fs, c1_w, nullptr, BATCH * HW, CC, DD, nullptr, bn1_g, bn1_b, p_Fnhwc, p_Fo1h, p_Fo1l);

    // conv2: Fo1(512) -> cat[:,0:512) bf16 pair
    k_conv_mma<<<dim3(HH / 4, BATCH, 4), 512, CONV_SMEM>>>(
        p_Fo1h, p_Fo1l, CC, p_w2h, p_w2l, 512, bn2_g, bn2_b,
        nullptr, p_cath, p_catl, CIN3);
    // conv3: cat(2560) -> x3 fp32
    k_conv_mma<<<dim3(HH / 4, BATCH, 4), 512, CONV_SMEM>>>(
        p_cath, p_catl, CIN3, p_w3h, p_w3l, 512, bn3_g, bn3_b,
        p_x3, nullptr, nullptr, CC);

    k_classifier<<<(BATCH * HW) / 64, 256>>>(drop_w, out);
}

// round 6
// speedup vs baseline: 5.5157x; 1.0689x over previous
#include <cuda_runtime.h>
#include <cuda_bf16.h>
#include <mma.h>
#include <math.h>
#include <stdint.h>

using namespace nvcuda;
typedef __nv_bfloat16 bf16;

#define EPS 1e-5f

#define BATCH 4
#define HH 64
#define WW 64
#define HW 4096
#define CC 512
#define KK 19
#define PP 64
#define NN 64
#define DD 256
#define CIN3 2560

// ---------------- scratch ----------------
__device__ float g_Fnhwc[BATCH * HW * CC];
__device__ float g_Fl[BATCH * PP * KK * CC];
__device__ float g_Fl2[BATCH * PP * KK * CC];
__device__ float g_Fg[BATCH * KK * CC];
__device__ float g_query[BATCH * HW * DD];
__device__ float g_key[BATCH * PP * KK * DD];
__device__ float g_value[BATCH * KK * DD];
__device__ float g_x3[BATCH * HW * CC];

// bf16 hi/lo pairs (activations)
__device__ bf16 g_Fh[BATCH * HW * CC];
__device__ bf16 g_Flo[BATCH * HW * CC];
__device__ bf16 g_hh[BATCH * PP * KK * CC];
__device__ bf16 g_hl[BATCH * PP * KK * CC];
__device__ bf16 g_Fl2h[BATCH * PP * KK * CC];
__device__ bf16 g_Fl2l[BATCH * PP * KK * CC];
__device__ bf16 g_Fsh[BATCH * HW * DD];
__device__ bf16 g_Fsl[BATCH * HW * DD];
__device__ bf16 g_cath[(size_t)BATCH * HW * CIN3];
__device__ bf16 g_catl[(size_t)BATCH * HW * CIN3];
__device__ bf16 g_Fo1h[BATCH * HW * CC];
__device__ bf16 g_Fo1l[BATCH * HW * CC];

// bf16 hi/lo pairs (weights)
__device__ bf16 g_w2h[512 * 512 * 9];
__device__ bf16 g_w2l[512 * 512 * 9];
__device__ bf16 g_w3h[512 * 2560 * 9];
__device__ bf16 g_w3l[512 * 2560 * 9];
__device__ bf16 g_qwh[512 * 256], g_qwl[512 * 256];     // [K=512][N=256]
__device__ bf16 g_kwh[512 * 256], g_kwl[512 * 256];
__device__ bf16 g_lgwh[512 * 512], g_lgwl[512 * 512];   // [K=512][N=512]
__device__ bf16 g_c1h[256 * 512], g_c1l[256 * 512];     // [K=256][N=512]

__device__ __forceinline__ void split_bf16(float v, bf16& hi, bf16& lo) {
    hi = __float2bfloat16(v);
    lo = __float2bfloat16(v - __bfloat162float(hi));
}

// cp.async helpers
__device__ __forceinline__ void cpa16(void* sdst, const void* gsrc, bool pred) {
    unsigned int s = (unsigned int)__cvta_generic_to_shared(sdst);
    int sz = pred ? 16 : 0;
    asm volatile("cp.async.cg.shared.global [%0], [%1], 16, %2;" :: "r"(s), "l"(gsrc), "r"(sz));
}
__device__ __forceinline__ void cpa_commit() {
    asm volatile("cp.async.commit_group;");
}
template <int N>
__device__ __forceinline__ void cpa_wait() {
    asm volatile("cp.async.wait_group %0;" :: "n"(N));
}

// ---------------- transpose NCHW -> NHWC: fp32 + bf16 pair ----------------
__global__ void k_transpose_f(const float* __restrict__ in, float* __restrict__ out,
                              bf16* __restrict__ oh, bf16* __restrict__ ol) {
    __shared__ float tile[32][33];
    int b = blockIdx.z;
    int hw0 = blockIdx.x * 32, c0 = blockIdx.y * 32;
    int tx = threadIdx.x, ty = threadIdx.y;
    for (int i = ty; i < 32; i += 8)
        tile[i][tx] = in[((size_t)b * CC + c0 + i) * HW + hw0 + tx];
    __syncthreads();
    for (int i = ty; i < 32; i += 8) {
        float v = tile[tx][i];
        size_t o = ((size_t)b * HW + hw0 + i) * CC + c0 + tx;
        out[o] = v;
        bf16 hi, lo; split_bf16(v, hi, lo);
        oh[o] = hi; ol[o] = lo;
    }
}

// ---------------- transpose NCHW -> NHWC (bf16 hi/lo only) ----------------
__global__ void k_transpose_pair(const float* __restrict__ in, bf16* __restrict__ oh,
                                 bf16* __restrict__ ol, int C, int out_stride, int col_off) {
    __shared__ float tile[32][33];
    int b = blockIdx.z;
    int hw0 = blockIdx.x * 32, c0 = blockIdx.y * 32;
    int tx = threadIdx.x, ty = threadIdx.y;
    for (int i = ty; i < 32; i += 8)
        tile[i][tx] = in[((size_t)b * C + c0 + i) * HW + hw0 + tx];
    __syncthreads();
    for (int i = ty; i < 32; i += 8) {
        float v = tile[tx][i];
        bf16 hi, lo; split_bf16(v, hi, lo);
        size_t o = ((size_t)b * HW + hw0 + i) * out_stride + col_off + c0 + tx;
        oh[o] = hi; ol[o] = lo;
    }
}

// ---------------- conv weight split, dst-ordered: OIHW -> [(ky*3+kx)][Cin][OutC] ----------------
__global__ void k_wsplit(const float* __restrict__ w, bf16* __restrict__ oh,
                         bf16* __restrict__ ol, int OutC, int Cin) {
    size_t d = (size_t)blockIdx.x * 256 + threadIdx.x;
    size_t total = (size_t)OutC * Cin * 9;
    if (d >= total) return;
    int o = d % OutC;
    size_t t2 = d / OutC;
    int i = t2 % Cin;
    int kq = t2 / Cin;
    float v = w[((size_t)o * Cin + i) * 9 + kq];
    bf16 hi, lo; split_bf16(v, hi, lo);
    oh[d] = hi; ol[d] = lo;
}

// ---------------- GEMM weight transpose+split: w[N,K] -> wt[K][N] pair ----------------
__global__ void k_wtsplit(const float* __restrict__ w, bf16* __restrict__ oh,
                          bf16* __restrict__ ol, int K, int N) {
    int d = blockIdx.x * 256 + threadIdx.x;
    if (d >= K * N) return;
    int k = d / N, n = d % N;
    float v = w[(size_t)n * K + k];
    bf16 hi, lo; split_bf16(v, hi, lo);
    oh[d] = hi; ol[d] = lo;
}

// ---------------- patch softmax + F_l ----------------
__global__ void k_patch_fl(const float* __restrict__ I, const float* __restrict__ R) {
    int bp = blockIdx.x;
    int b = bp >> 6, p = bp & 63;
    int ph = p >> 3, pw = p & 7;
    int tid = threadIdx.x;

    __shared__ float lg[KK][NN];
    __shared__ float pix[NN][20];
    __shared__ float bc[KK];
    __shared__ float Fp[NN][65];

    for (int idx = tid; idx < KK * NN; idx += 256) {
        int k = idx / NN, n = idx % NN;
        int h = ph * 8 + (n >> 3), w = pw * 8 + (n & 7);
        lg[k][n] = I[(((size_t)b * KK + k) * HH + h) * WW + w];
    }
    if (tid < KK) bc[tid] = R[((size_t)b * KK + tid) * PP + p];
    __syncthreads();

    if (tid < KK) {
        float mx = -1e30f;
        for (int n = 0; n < NN; n++) mx = fmaxf(mx, lg[tid][n]);
        float s = 0.f;
        for (int n = 0; n < NN; n++) { float e = __expf(lg[tid][n] - mx); pix[n][tid] = e; s += e; }
        float inv = 1.f / s;
        for (int n = 0; n < NN; n++) pix[n][tid] *= inv;
    }
    __syncthreads();

    for (int c0 = 0; c0 < CC; c0 += 64) {
        for (int idx = tid; idx < NN * 64; idx += 256) {
            int n = idx >> 6, cc = idx & 63;
            int h = ph * 8 + (n >> 3), w = pw * 8 + (n & 7);
            Fp[n][cc] = g_Fnhwc[((size_t)b * HW + h * WW + w) * CC + c0 + cc];
        }
        __syncthreads();
        for (int o = tid; o < KK * 64; o += 256) {
            int k = o >> 6, cc = o & 63;
            float acc = 0.f;
            #pragma unroll 8
            for (int n = 0; n < NN; n++) acc += pix[n][k] * Fp[n][cc];
            g_Fl[((size_t)bp * KK + k) * CC + c0 + cc] = acc * bc[k];
        }
        __syncthreads();
    }
}

// ---------------- h = relu(lg_w1 @p F_l + F_l) -> bf16 pair ----------------
__global__ void k_lg1(const float* __restrict__ lg_w1) {
    int c0 = blockIdx.x * 64;
    int bk = blockIdx.y;
    int b = bk / KK, k = bk % KK;
    int tid = threadIdx.x;
    __shared__ float w1[64][64];
    __shared__ float Fl[64][65];
    for (int idx = tid; idx < 4096; idx += 256) w1[idx >> 6][idx & 63] = lg_w1[idx];
    for (int idx = tid; idx < 4096; idx += 256) {
        int p = idx >> 6, cc = idx & 63;
        Fl[p][cc] = g_Fl[(((size_t)b * PP + p) * KK + k) * CC + c0 + cc];
    }
    __syncthreads();
    for (int o = tid; o < 4096; o += 256) {
        int q = o >> 6, cc = o & 63;
        float acc = Fl[q][cc];
        #pragma unroll 8
        for (int p = 0; p < 64; p++) acc += w1[q][p] * Fl[p][cc];
        float v = fmaxf(acc, 0.f);
        bf16 hi, lo; split_bf16(v, hi, lo);
        size_t oidx = (((size_t)b * PP + q) * KK + k) * CC + c0 + cc;
        g_hh[oidx] = hi; g_hl[oidx] = lo;
    }
}

// ---------------- legacy fp32 SIMT GEMM (only for tiny value GEMM) ----------------
__global__ void k_gemm_v(const float* __restrict__ A, const float* __restrict__ Bw,
                         float* __restrict__ C, int M, int N, int K,
                         const float* __restrict__ bias) {
    __shared__ float As[16][68];
    __shared__ float Bs[16][68];
    int m0 = blockIdx.y * 64, n0 = blockIdx.x * 64;
    int tid = threadIdx.x;
    int tx = tid & 15, ty = tid >> 4;
    float acc[4][4] = {};

    for (int k0 = 0; k0 < K; k0 += 16) {
        for (int idx = tid; idx < 64 * 16; idx += 256) {
            int i = idx >> 4, kk = idx & 15;
            int m = m0 + i;
            As[kk][i] = (m < M) ? A[(size_t)m * K + k0 + kk] : 0.f;
        }
        for (int idx = tid; idx < 64 * 16; idx += 256) {
            int j = idx >> 4, kk = idx & 15;
            Bs[kk][j] = Bw[(size_t)(n0 + j) * K + k0 + kk];
        }
        __syncthreads();
        #pragma unroll
        for (int kk = 0; kk < 16; kk++) {
            float a[4], bv[4];
            #pragma unroll
            for (int i = 0; i < 4; i++) a[i] = As[kk][ty * 4 + i];
            #pragma unroll
            for (int j = 0; j < 4; j++) bv[j] = Bs[kk][tx * 4 + j];
            #pragma unroll
            for (int i = 0; i < 4; i++)
                #pragma unroll
                for (int j = 0; j < 4; j++) acc[i][j] += a[i] * bv[j];
        }
        __syncthreads();
    }

    #pragma unroll
    for (int i = 0; i < 4; i++) {
        int m = m0 + ty * 4 + i;
        if (m >= M) continue;
        #pragma unroll
        for (int j = 0; j < 4; j++) {
            int n = n0 + tx * 4 + j;
            C[(size_t)m * N + n] = acc[i][j] + bias[n];
        }
    }
}

// ---------------- fuse ----------------
__global__ void k_fuse(const float* __restrict__ fuse_w, const float* __restrict__ fuse_b) {
    int bk = blockIdx.x;
    int c = threadIdx.x;
    int b = bk / KK, k = bk % KK;
    float acc = fuse_b[0];
    #pragma unroll 8
    for (int p = 0; p < PP; p++)
        acc += fuse_w[p] * g_Fl2[(((size_t)b * PP + p) * KK + k) * CC + c];
    g_Fg[(size_t)bk * CC + c] = acc;
}

// ---------------- attention (writes F_s bf16 pair) ----------------
__global__ void k_attn() {
    int bp = blockIdx.x;
    int b = bp >> 6, p = bp & 63;
    int ph = p >> 3, pw = p & 7;
    int tid = threadIdx.x;
    __shared__ float ks[KK][DD];
    __shared__ float vs[KK][DD];
    for (int idx = tid; idx < KK * DD; idx += 256)
        ((float*)ks)[idx] = g_key[(size_t)bp * KK * DD + idx];
    for (int idx = tid; idx < KK * DD; idx += 256)
        ((float*)vs)[idx] = g_value[(size_t)b * KK * DD + idx];
    __syncthreads();

    int warp = tid >> 5, lane = tid & 31;
    for (int n = warp; n < NN; n += 8) {
        int h = ph * 8 + (n >> 3), w = pw * 8 + (n & 7);
        const float* qrow = &g_query[((size_t)b * HW + h * WW + w) * DD];
        float qr[8];
        #pragma unroll
        for (int i = 0; i < 8; i++) qr[i] = qrow[i * 32 + lane];

        float acc[KK];
        #pragma unroll
        for (int k = 0; k < KK; k++) acc[k] = 0.f;
        #pragma unroll
        for (int i = 0; i < 8; i++) {
            float qd = qr[i];
            #pragma unroll
            for (int k = 0; k < KK; k++) acc[k] += qd * ks[k][i * 32 + lane];
        }
        #pragma unroll
        for (int k = 0; k < KK; k++) {
            #pragma unroll
            for (int off = 16; off > 0; off >>= 1)
                acc[k] += __shfl_xor_sync(0xFFFFFFFFu, acc[k], off);
        }
        float mx = -1e30f;
        #pragma unroll
        for (int k = 0; k < KK; k++) mx = fmaxf(mx, acc[k]);
        float sum = 0.f;
        #pragma unroll
        for (int k = 0; k < KK; k++) { acc[k] = __expf(acc[k] - mx); sum += acc[k]; }
        float inv = 1.f / sum;
        #pragma unroll
        for (int k = 0; k < KK; k++) acc[k] *= inv;

        size_t obase = ((size_t)b * HW + h * WW + w) * DD;
        #pragma unroll
        for (int i = 0; i < 8; i++) {
            int d = i * 32 + lane;
            float o = 0.f;
            #pragma unroll
            for (int k = 0; k < KK; k++) o += acc[k] * vs[k][d];
            bf16 hi, lo; split_bf16(o, hi, lo);
            g_Fsh[obase + d] = hi; g_Fsl[obase + d] = lo;
        }
    }
}

// ---------------- generic split-bf16 wmma GEMM: C[M,N] = A[M,K] @ Wt[K,N] ----------------
// block: M0=256 x N0=128, 512 threads (16 warps = 8 warpM x 2 warpN)
// MODE 0: fp32 C + bf16 pair   MODE 1: +bias fp32   MODE 2: resid + relu(bn) -> pair
// Stage: Ah[256*16]=8192B | Al=8192B | Wh[16*136]=4352B | Wl=4352B = 25088B
#define GSTAGE_B 25088
template <int MODE>
__global__ __launch_bounds__(512)
void k_gemm_mma(const bf16* __restrict__ Ahg, const bf16* __restrict__ Alg,
                const bf16* __restrict__ Wth, const bf16* __restrict__ Wtl,
                int K, int N,
                float* __restrict__ Cf, bf16* __restrict__ Ch, bf16* __restrict__ Cl,
                const float* __restrict__ bias,
                const float* __restrict__ bng, const float* __restrict__ bnb,
                const float* __restrict__ resid) {
    extern __shared__ char smem[];
    int n0 = blockIdx.x * 128, m0 = blockIdx.y * 256;
    int tid = threadIdx.x;
    int lane = tid & 31, warp = tid >> 5;
    int warpM = warp >> 1, warpN = warp & 1;
    int iters = K >> 4;

    wmma::fragment<wmma::accumulator, 16, 16, 16, float> acc[2][4];
    #pragma unroll
    for (int mt = 0; mt < 2; mt++)
        #pragma unroll
        for (int nj = 0; nj < 4; nj++) wmma::fill_fragment(acc[mt][nj], 0.f);

    auto issue = [&](int it) {
        int k0 = it << 4;
        char* base = smem + (it & 1) * GSTAGE_B;
        bf16* Ah = (bf16*)base;
        bf16* Al = (bf16*)(base + 8192);
        bf16* Wh = (bf16*)(base + 16384);
        bf16* Wl = (bf16*)(base + 20736);
        // A: 256 rows x 16 ch (hi 512 uint4 + lo 512)
        for (int u = tid; u < 1024; u += 512) {
            int v = (u < 512) ? u : u - 512;
            int flat = v * 8;
            int r = flat >> 4, c8 = flat & 15;
            const bf16* src = (u < 512) ? Ahg : Alg;
            const bf16* g = src + (size_t)(m0 + r) * K + k0 + c8;
            bf16* dst = ((u < 512) ? Ah : Al) + flat;
            cpa16(dst, g, true);
        }
        // W: 16 k x 128 n (hi 256 uint4 + lo 256), padded rows (136)
        if (tid < 512) {
            int u = tid;
            if (u < 512) {
                int v = (u < 256) ? u : u - 256;
                int flat = v * 8;
                int kk = flat >> 7, n8 = flat & 127;
                const bf16* src = (u < 256) ? Wth : Wtl;
                const bf16* g = src + (size_t)(k0 + kk) * N + n0 + n8;
                bf16* dst = ((u < 256) ? Wh : Wl) + kk * 136 + n8;
                cpa16(dst, g, true);
            }
        }
        cpa_commit();
    };

    issue(0);

    for (int it = 0; it < iters; it++) {
        cpa_wait<0>();
        __syncthreads();
        if (it + 1 < iters) issue(it + 1);

        char* base = smem + (it & 1) * GSTAGE_B;
        bf16* Ah = (bf16*)base;
        bf16* Al = (bf16*)(base + 8192);
        bf16* Wh = (bf16*)(base + 16384);
        bf16* Wl = (bf16*)(base + 20736);

        #pragma unroll
        for (int mt = 0; mt < 2; mt++) {
            int t = warpM * 2 + mt;
            wmma::fragment<wmma::matrix_a, 16, 16, 16, bf16, wmma::row_major> ah, al;
            wmma::load_matrix_sync(ah, Ah + t * 256, 16);
            wmma::load_matrix_sync(al, Al + t * 256, 16);
            #pragma unroll
            for (int nj = 0; nj < 4; nj++) {
                wmma::fragment<wmma::matrix_b, 16, 16, 16, bf16, wmma::row_major> bh, bl;
                int boff = warpN * 64 + nj * 16;
                wmma::load_matrix_sync(bh, Wh + boff, 136);
                wmma::load_matrix_sync(bl, Wl + boff, 136);
                wmma::mma_sync(acc[mt][nj], ah, bh, acc[mt][nj]);
                wmma::mma_sync(acc[mt][nj], ah, bl, acc[mt][nj]);
                wmma::mma_sync(acc[mt][nj], al, bh, acc[mt][nj]);
            }
        }
        __syncthreads();
    }

    // epilogue (per-warp staged)
    float* buf = (float*)smem + warp * 320;
    #pragma unroll
    for (int mt = 0; mt < 2; mt++) {
        int t = warpM * 2 + mt;
        #pragma unroll
        for (int nj = 0; nj < 4; nj++) {
            wmma::store_matrix_sync(buf, acc[mt][nj], 20, wmma::mem_row_major);
            __syncwarp();
            #pragma unroll
            for (int l = 0; l < 8; l++) {
                int e = l * 32 + lane;
                int r = e >> 4, c = e & 15;
                int gm = m0 + t * 16 + r;
                int gn = n0 + warpN * 64 + nj * 16 + c;
                float v = buf[r * 20 + c];
                size_t o = (size_t)gm * N + gn;
                if (MODE == 0) {
                    Cf[o] = v;
                    bf16 hi, lo; split_bf16(v, hi, lo);
                    Ch[o] = hi; Cl[o] = lo;
                } else if (MODE == 1) {
                    Cf[o] = v + bias[gn];
                } else {
                    float s = bng[gn] * rsqrtf(1.f + EPS);
                    v = resid[o] + fmaxf(v * s + bnb[gn], 0.f);
                    bf16 hi, lo; split_bf16(v, hi, lo);
                    Ch[o] = hi; Cl[o] = lo;
                }
            }
            __syncwarp();
        }
    }
}

// ---------------- tensor-core 3x3 conv (unchanged from R5) ----------------
#define STAGE_B 43008
__global__ __launch_bounds__(512, 1)
void k_conv_mma(const bf16* __restrict__ in_hi, const bf16* __restrict__ in_lo, int Cin,
                const bf16* __restrict__ w_hi, const bf16* __restrict__ w_lo, int OutC,
                const float* __restrict__ bng, const float* __restrict__ bnb,
                float* __restrict__ out_f,
                bf16* __restrict__ out_hi, bf16* __restrict__ out_lo,
                int out_stride) {
    extern __shared__ char smem[];
    int h0 = blockIdx.x * 4, b = blockIdx.y, n0 = blockIdx.z * 128;
    int tid = threadIdx.x;
    int lane = tid & 31, warp = tid >> 5;
    int warpM = warp >> 1, warpN = warp & 1;
    int csteps = Cin >> 4;
    int iters = 3 * csteps;

    wmma::fragment<wmma::accumulator, 16, 16, 16, float> acc[2][4];
    #pragma unroll
    for (int mt = 0; mt < 2; mt++)
        #pragma unroll
        for (int nj = 0; nj < 4; nj++) wmma::fill_fragment(acc[mt][nj], 0.f);

    auto issue = [&](int it) {
        int ky = it / csteps;
        int c0 = (it - ky * csteps) << 4;
        char* base = smem + (it & 1) * STAGE_B;
        bf16* Ah = (bf16*)base;
        bf16* Al = (bf16*)(base + 8448);
        bf16* Wh = (bf16*)(base + 16896);
        bf16* Wl = (bf16*)(base + 29952);
        for (int u = tid; u < 1056; u += 512) {
            int v = (u < 528) ? u : u - 528;
            int flat = v * 8;
            int r = flat / 1056, rem = flat % 1056;
            int wi = rem >> 4, c8 = rem & 15;
            int gh = h0 + r + ky - 1, gw = wi - 1;
            bool pred = (gh >= 0 && gh < HH && gw >= 0 && gw < WW);
            const bf16* src = (u < 528) ? in_hi : in_lo;
            const bf16* g = pred ? (src + ((size_t)(b * HH + gh) * WW + gw) * Cin + c0 + c8) : src;
            bf16* dst = ((u < 528) ? Ah : Al) + (r * 66 + wi) * 16 + c8;
            cpa16(dst, g, pred);
        }
        for (int u = tid; u < 1536; u += 512) {
            int v = (u < 768) ? u : u - 768;
            int flat = v * 8;
            int kx = flat >> 11, rem = flat & 2047;
            int ck = rem >> 7, o8 = rem & 127;
            const bf16* src = (u < 768) ? w_hi : w_lo;
            const bf16* g = src + ((size_t)(ky * 3 + kx) * Cin + c0 + ck) * OutC + n0 + o8;
            bf16* dst = ((u < 768) ? Wh : Wl) + kx * 2176 + ck * 136 + o8;
            cpa16(dst, g, true);
        }
        cpa_commit();
    };

    issue(0);

    for (int it = 0; it < iters; it++) {
        cpa_wait<0>();
        __syncthreads();
        if (it + 1 < iters) issue(it + 1);

        char* base = smem + (it & 1) * STAGE_B;
        bf16* Ah = (bf16*)base;
        bf16* Al = (bf16*)(base + 8448);
        bf16* Wh = (bf16*)(base + 16896);
        bf16* Wl = (bf16*)(base + 29952);

        #pragma unroll
        for (int mt = 0; mt < 2; mt++) {
            int t = warpM * 2 + mt;
            int pbase = (t >> 2) * 66 + (t & 3) * 16;
            #pragma unroll
            for (int kx = 0; kx < 3; kx++) {
                wmma::fragment<wmma::matrix_a, 16, 16, 16, bf16, wmma::row_major> ah, al;
                wmma::load_matrix_sync(ah, Ah + (pbase + kx) * 16, 16);
                wmma::load_matrix_sync(al, Al + (pbase + kx) * 16, 16);
                #pragma unroll
                for (int nj = 0; nj < 4; nj++) {
                    wmma::fragment<wmma::matrix_b, 16, 16, 16, bf16, wmma::row_major> bh, bl;
                    int boff = kx * 2176 + warpN * 64 + nj * 16;
                    wmma::load_matrix_sync(bh, Wh + boff, 136);
                    wmma::load_matrix_sync(bl, Wl + boff, 136);
                    wmma::mma_sync(acc[mt][nj], ah, bh, acc[mt][nj]);
                    wmma::mma_sync(acc[mt][nj], ah, bl, acc[mt][nj]);
                    wmma::mma_sync(acc[mt][nj], al, bh, acc[mt][nj]);
                }
            }
        }
        __syncthreads();
    }

    float* buf = (float*)smem + warp * 320;
    #pragma unroll
    for (int mt = 0; mt < 2; mt++) {
        int t = warpM * 2 + mt;
        int row_l = t >> 2, px0 = (t & 3) * 16;
        size_t rowbase = (size_t)(b * HH + h0 + row_l) * WW;
        #pragma unroll
        for (int nj = 0; nj < 4; nj++) {
            wmma::store_matrix_sync(buf, acc[mt][nj], 20, wmma::mem_row_major);
            __syncwarp();
            #pragma unroll
            for (int l = 0; l < 8; l++) {
                int e = l * 32 + lane;
                int r = e >> 4, c = e & 15;
                int gn = n0 + warpN * 64 + nj * 16 + c;
                float v = buf[r * 20 + c];
                float s = bng[gn] * rsqrtf(1.f + EPS);
                v = fmaxf(v * s + bnb[gn], 0.f);
                size_t o = (rowbase + px0 + r) * out_stride + gn;
                if (out_f) {
                    out_f[o] = v;
                } else {
                    bf16 hi, lo; split_bf16(v, hi, lo);
                    out_hi[o] = hi; out_lo[o] = lo;
                }
            }
            __syncwarp();
        }
    }
}

// ---------------- final 1x1 classifier -> NCHW ----------------
__global__ void k_classifier(const float* __restrict__ drop_w, float* __restrict__ out) {
    __shared__ float Xs[32][65];
    __shared__ float Ws[KK][33];
    int tid = threadIdx.x;
    int row0 = blockIdx.x * 64;
    int b = row0 >> 12;
    int hw0 = row0 & 4095;
    float acc[5] = {0.f, 0.f, 0.f, 0.f, 0.f};

    for (int c0 = 0; c0 < CC; c0 += 32) {
        for (int idx = tid; idx < 64 * 32; idx += 256) {
            int r = idx >> 5, cc = idx & 31;
            Xs[cc][r] = g_x3[(size_t)(row0 + r) * CC + c0 + cc];
        }
        for (int idx = tid; idx < KK * 32; idx += 256) {
            int k = idx >> 5, cc = idx & 31;
            Ws[k][cc] = drop_w[(size_t)k * CC + c0 + cc];
        }
        __syncthreads();
        #pragma unroll
        for (int sIdx = 0; sIdx < 5; sIdx++) {
            int o = tid + sIdx * 256;
            if (o < KK * 64) {
                int k = o >> 6, r = o & 63;
                float a = acc[sIdx];
                #pragma unroll 8
                for (int cc = 0; cc < 32; cc++) a += Ws[k][cc] * Xs[cc][r];
                acc[sIdx] = a;
            }
        }
        __syncthreads();
    }
    #pragma unroll
    for (int sIdx = 0; sIdx < 5; sIdx++) {
        int o = tid + sIdx * 256;
        if (o < KK * 64) {
            int k = o >> 6, r = o & 63;
            out[((size_t)b * KK + k) * HW + hw0 + r] = acc[sIdx];
        }
    }
}

// ---------------- launch ----------------
extern "C" void kernel_launch(void* const* d_in, const int* in_sizes, int n_in,
                              void* d_out, int out_size) {
    const float* M_1   = (const float*)d_in[0];
    const float* F     = (const float*)d_in[1];
    const float* I     = (const float*)d_in[2];
    const float* R     = (const float*)d_in[3];
    const float* lg_w1 = (const float*)d_in[4];
    const float* lg_w2 = (const float*)d_in[5];
    const float* fuse_w= (const float*)d_in[6];
    const float* fuse_b= (const float*)d_in[7];
    const float* q_w   = (const float*)d_in[8];
    const float* q_b   = (const float*)d_in[9];
    const float* k_w   = (const float*)d_in[10];
    const float* k_b   = (const float*)d_in[11];
    const float* v_w   = (const float*)d_in[12];
    const float* v_b   = (const float*)d_in[13];
    const float* c1_w  = (const float*)d_in[14];
    const float* bn1_g = (const float*)d_in[15];
    const float* bn1_b = (const float*)d_in[16];
    const float* c2_w  = (const float*)d_in[17];
    const float* bn2_g = (const float*)d_in[18];
    const float* bn2_b = (const float*)d_in[19];
    const float* c3_w  = (const float*)d_in[20];
    const float* bn3_g = (const float*)d_in[21];
    const float* bn3_b = (const float*)d_in[22];
    const float* drop_w= (const float*)d_in[23];
    float* out = (float*)d_out;

    float *p_Fnhwc, *p_Fl, *p_Fl2, *p_Fg, *p_q, *p_k, *p_v, *p_x3;
    bf16 *p_Fh, *p_Flo, *p_hh, *p_hl, *p_Fl2h, *p_Fl2l, *p_Fsh, *p_Fsl;
    bf16 *p_cath, *p_catl, *p_Fo1h, *p_Fo1l;
    bf16 *p_w2h, *p_w2l, *p_w3h, *p_w3l;
    bf16 *p_qwh, *p_qwl, *p_kwh, *p_kwl, *p_lgwh, *p_lgwl, *p_c1h, *p_c1l;
    cudaGetSymbolAddress((void**)&p_Fnhwc, g_Fnhwc);
    cudaGetSymbolAddress((void**)&p_Fl,    g_Fl);
    cudaGetSymbolAddress((void**)&p_Fl2,   g_Fl2);
    cudaGetSymbolAddress((void**)&p_Fg,    g_Fg);
    cudaGetSymbolAddress((void**)&p_q,     g_query);
    cudaGetSymbolAddress((void**)&p_k,     g_key);
    cudaGetSymbolAddress((void**)&p_v,     g_value);
    cudaGetSymbolAddress((void**)&p_x3,    g_x3);
    cudaGetSymbolAddress((void**)&p_Fh,    g_Fh);
    cudaGetSymbolAddress((void**)&p_Flo,   g_Flo);
    cudaGetSymbolAddress((void**)&p_hh,    g_hh);
    cudaGetSymbolAddress((void**)&p_hl,    g_hl);
    cudaGetSymbolAddress((void**)&p_Fl2h,  g_Fl2h);
    cudaGetSymbolAddress((void**)&p_Fl2l,  g_Fl2l);
    cudaGetSymbolAddress((void**)&p_Fsh,   g_Fsh);
    cudaGetSymbolAddress((void**)&p_Fsl,   g_Fsl);
    cudaGetSymbolAddress((void**)&p_cath,  g_cath);
    cudaGetSymbolAddress((void**)&p_catl,  g_catl);
    cudaGetSymbolAddress((void**)&p_Fo1h,  g_Fo1h);
    cudaGetSymbolAddress((void**)&p_Fo1l,  g_Fo1l);
    cudaGetSymbolAddress((void**)&p_w2h,   g_w2h);
    cudaGetSymbolAddress((void**)&p_w2l,   g_w2l);
    cudaGetSymbolAddress((void**)&p_w3h,   g_w3h);
    cudaGetSymbolAddress((void**)&p_w3l,   g_w3l);
    cudaGetSymbolAddress((void**)&p_qwh,   g_qwh);
    cudaGetSymbolAddress((void**)&p_qwl,   g_qwl);
    cudaGetSymbolAddress((void**)&p_kwh,   g_kwh);
    cudaGetSymbolAddress((void**)&p_kwl,   g_kwl);
    cudaGetSymbolAddress((void**)&p_lgwh,  g_lgwh);
    cudaGetSymbolAddress((void**)&p_lgwl,  g_lgwl);
    cudaGetSymbolAddress((void**)&p_c1h,   g_c1h);
    cudaGetSymbolAddress((void**)&p_c1l,   g_c1l);

    dim3 blk32(32, 8);
    const int CONV_SMEM = 2 * STAGE_B;     // 86016 B
    const int GEMM_SMEM = 2 * GSTAGE_B;    // 50176 B
    cudaFuncSetAttribute(k_conv_mma, cudaFuncAttributeMaxDynamicSharedMemorySize, CONV_SMEM);
    cudaFuncSetAttribute(k_gemm_mma<0>, cudaFuncAttributeMaxDynamicSharedMemorySize, GEMM_SMEM);
    cudaFuncSetAttribute(k_gemm_mma<1>, cudaFuncAttributeMaxDynamicSharedMemorySize, GEMM_SMEM);
    cudaFuncSetAttribute(k_gemm_mma<2>, cudaFuncAttributeMaxDynamicSharedMemorySize, GEMM_SMEM);

    // weight prep
    k_wsplit<<<(512 * 512 * 9 + 255) / 256, 256>>>(c2_w, p_w2h, p_w2l, 512, 512);
    k_wsplit<<<(512 * 2560 * 9 + 255) / 256, 256>>>(c3_w, p_w3h, p_w3l, 512, 2560);
    k_wtsplit<<<(512 * 256 + 255) / 256, 256>>>(q_w, p_qwh, p_qwl, 512, 256);
    k_wtsplit<<<(512 * 256 + 255) / 256, 256>>>(k_w, p_kwh, p_kwl, 512, 256);
    k_wtsplit<<<(512 * 512 + 255) / 256, 256>>>(lg_w2, p_lgwh, p_lgwl, 512, 512);
    k_wtsplit<<<(256 * 512 + 255) / 256, 256>>>(c1_w, p_c1h, p_c1l, 256, 512);

    // activations prep
    k_transpose_f<<<dim3(HW / 32, CC / 32, BATCH), blk32>>>(F, p_Fnhwc, p_Fh, p_Flo);
    k_transpose_pair<<<dim3(HW / 32, 2048 / 32, BATCH), blk32>>>(M_1, p_cath, p_catl, 2048, CIN3, CC);
    k_patch_fl<<<BATCH * PP, 256>>>(I, R);
    k_lg1<<<dim3(CC / 64, BATCH * KK), 256>>>(lg_w1);

    // Fl2 = h @ lg_w2^T : [4864,512] x [512,512]
    k_gemm_mma<0><<<dim3(512 / 128, 4864 / 256), 512, GEMM_SMEM>>>(
        p_hh, p_hl, p_lgwh, p_lgwl, 512, 512, p_Fl2, p_Fl2h, p_Fl2l,
        nullptr, nullptr, nullptr, nullptr);
    k_fuse<<<BATCH * KK, CC>>>(fuse_w, fuse_b);

    // query = F @ q_w^T + q_b : [16384,512] x [512,256]
    k_gemm_mma<1><<<dim3(256 / 128, 16384 / 256), 512, GEMM_SMEM>>>(
        p_Fh, p_Flo, p_qwh, p_qwl, 512, 256, p_q, nullptr, nullptr,
        q_b, nullptr, nullptr, nullptr);
    // key = Fl2 @ k_w^T + k_b : [4864,512] x [512,256]
    k_gemm_mma<1><<<dim3(256 / 128, 4864 / 256), 512, GEMM_SMEM>>>(
        p_Fl2h, p_Fl2l, p_kwh, p_kwl, 512, 256, p_k, nullptr, nullptr,
        k_b, nullptr, nullptr, nullptr);
    // value (tiny, fp32 SIMT)
    k_gemm_v<<<dim3(DD / 64, (BATCH * KK + 63) / 64), 256>>>(
        p_Fg, v_w, p_v, BATCH * KK, DD, CC, v_b);

    k_attn<<<BATCH * PP, 256>>>();

    // Fo1 = F + relu(bn1(F_s @ c1_w^T)) : [16384,256] x [256,512] -> pair
    k_gemm_mma<2><<<dim3(512 / 128, 16384 / 256), 512, GEMM_SMEM>>>(
        p_Fsh, p_Fsl, p_c1h, p_c1l, 256, 512, nullptr, p_Fo1h, p_Fo1l,
        nullptr, bn1_g, bn1_b, p_Fnhwc);

    // conv2: Fo1(512) -> cat[:,0:512) bf16 pair
    k_conv_mma<<<dim3(HH / 4, BATCH, 4), 512, CONV_SMEM>>>(
        p_Fo1h, p_Fo1l, CC, p_w2h, p_w2l, 512, bn2_g, bn2_b,
        nullptr, p_cath, p_catl, CIN3);
    // conv3: cat(2560) -> x3 fp32
    k_conv_mma<<<dim3(HH / 4, BATCH, 4), 512, CONV_SMEM>>>(
        p_cath, p_catl, CIN3, p_w3h, p_w3l, 512, bn3_g, bn3_b,
        p_x3, nullptr, nullptr, CC);

    k_classifier<<<(BATCH * HW) / 64, 256>>>(drop_w, out);
}